// round 8
// baseline (speedup 1.0000x reference)
#include <cuda_runtime.h>
#include <cuda_fp16.h>
#include <cstdint>

#define NN 4096
#define TT 64
#define DIN_ 131
#define GIN_ 132

// ---------------- static device workspace ----------------
__device__ __half d_Ah[(size_t)NN * NN];      // row-normalized A fp16 (33.5 MB)
__device__ float  d_Dfac[NN];                 // D/(D+1e-8)
__device__ __half d_U16[NN * 256];            // [n][c*64+t] c=m,tf,tj; cols 192.. zero
__device__ __half d_P1[NN * 256];             // Anorm @ U
__device__ __half d_P2[NN * 256];             // Anorm @ P1
__device__ __half d_S[NN * 400];              // [h | G1 | G2 | aux9 | 0*6 | 1]
__device__ __half d_X[NN * 256];              // [msg | h]
__device__ float  d_hst[NN * 128];            // carried state fp32
__device__ float  d_logit[NN * 4];            // h @ mixW^T (raw)
__device__ float  d_Part[(size_t)4 * NN * 256]; // split-K partials
__device__ __half d_Wcat[400 * 512];          // folded Cheb weights + aux rows
__device__ __half d_W2[256 * 512];            // gate weights [rsum|zsum|i_n|h_n]
__device__ unsigned d_cnt[64];                // split-K tile tickets (mod-4)

#define CPA16(dst, src) asm volatile("cp.async.cg.shared.global [%0], [%1], 16;\n" :: "r"(dst), "l"(src))
#define CPCOMMIT() asm volatile("cp.async.commit_group;\n" ::)

// ---------------- prep kernels ----------------
__global__ void __launch_bounds__(256) rownorm_kernel(const float* __restrict__ A) {
    int n = blockIdx.x;
    const float* row = A + (size_t)n * NN;
    float s = 0.f;
    for (int j = threadIdx.x; j < NN; j += 256) s += row[j];
    __shared__ float red[256];
    red[threadIdx.x] = s;
    __syncthreads();
    for (int o = 128; o > 0; o >>= 1) {
        if (threadIdx.x < o) red[threadIdx.x] += red[threadIdx.x + o];
        __syncthreads();
    }
    float D = red[0];
    float Dinv = (D > 0.f) ? (1.0f / D) : 0.f;
    if (threadIdx.x == 0) d_Dfac[n] = D / (D + 1e-8f);
    __half* dst = d_Ah + (size_t)n * NN;
    for (int j = threadIdx.x; j < NN; j += 256) dst[j] = __float2half(row[j] * Dinv);
}

__global__ void __launch_bounds__(256) build_u_kernel(const float* __restrict__ m,
                                                      const float* __restrict__ tf,
                                                      const float* __restrict__ tj) {
    int i = blockIdx.x * 256 + threadIdx.x;
    if (i >= NN * 256) return;
    int n = i >> 8, c = i & 255;
    float v = 0.f;
    if (c < 64)        v = m[n * 64 + c];
    else if (c < 128)  v = tf[n * 64 + c - 64];
    else if (c < 192)  v = tj[n * 64 + c - 128];
    d_U16[i] = __float2half(v);
}

// W_msg layout [4][3][131][128]: ((p*3+k)*131 + d)*128 + j
__global__ void __launch_bounds__(256) build_w_kernel(const float* __restrict__ W_msg,
                                                      const float* __restrict__ W_ih,
                                                      const float* __restrict__ W_hh,
                                                      const float* __restrict__ b_msg) {
    int i = blockIdx.x * 256 + threadIdx.x;
    const int NWCAT = 400 * 512;
    const int NW2 = 256 * 512;
    if (i < NWCAT) {
        int d = i >> 9, qc = i & 511;
        int p = qc >> 7, j = qc & 127;
        float v = 0.f;
        if (d < 384) {
            int kc = d >> 7, c = d & 127;
            if (kc == 0)      v = W_msg[((p*3+0)*DIN_ + c)*128 + j] - W_msg[((p*3+2)*DIN_ + c)*128 + j];
            else if (kc == 1) v = W_msg[((p*3+1)*DIN_ + c)*128 + j];
            else              v = 2.f * W_msg[((p*3+2)*DIN_ + c)*128 + j];
        } else if (d < 393) {
            int a = d - 384, c = a / 3, wq = a % 3, dd = 128 + c;
            if (wq == 0)      v = W_msg[((p*3+0)*DIN_ + dd)*128 + j] - W_msg[((p*3+2)*DIN_ + dd)*128 + j];
            else if (wq == 1) v = W_msg[((p*3+1)*DIN_ + dd)*128 + j];
            else              v = 2.f * W_msg[((p*3+2)*DIN_ + dd)*128 + j];
        } else if (d == 399) {
            v = b_msg[p * 128 + j];
        }
        d_Wcat[i] = __float2half(v);
    } else if (i < NWCAT + NW2) {
        int r = i - NWCAT;
        int d = r >> 9, qc = r & 511;
        int blk = qc >> 7, j = qc & 127;
        float v = 0.f;
        if (blk == 0)      v = (d < 128) ? W_ih[(size_t)j * GIN_ + d] : W_hh[(size_t)j * 128 + (d - 128)];
        else if (blk == 1) v = (d < 128) ? W_ih[(size_t)(128+j) * GIN_ + d] : W_hh[(size_t)(128+j) * 128 + (d - 128)];
        else if (blk == 2) v = (d < 128) ? W_ih[(size_t)(256+j) * GIN_ + d] : 0.f;
        else               v = (d < 128) ? 0.f : W_hh[(size_t)(256+j) * 128 + (d - 128)];
        d_W2[r] = __float2half(v);
    }
}

__global__ void __launch_bounds__(256) init_kernel() {
    int i = blockIdx.x * 256 + threadIdx.x;
    if (i >= NN * 128) return;
    int n = i >> 7, j = i & 127;
    d_hst[i] = 0.f;
    d_S[n * 400 + j] = __float2half(0.f);
    d_X[n * 256 + 128 + j] = __float2half(0.f);
    if (i < NN * 4) d_logit[i] = 0.f;
    if (i < NN * 16) {
        int n2 = i >> 4, a = i & 15;
        if (a >= 9) d_S[n2 * 400 + 384 + a] = __float2half(a == 15 ? 1.0f : 0.0f);
    }
}

// aux cols for t=0 (written for t+1 by gate_kernel thereafter)
__global__ void __launch_bounds__(256) init_aux_kernel(const float* __restrict__ m,
                                                       const float* __restrict__ tf,
                                                       const float* __restrict__ tj) {
    int i = blockIdx.x * 256 + threadIdx.x;
    if (i >= NN * 9) return;
    int n = i / 9, a = i - n * 9, c = a / 3, q = a % 3;
    __half v;
    if (q == 0) {
        const float* src = (c == 0) ? m : (c == 1 ? tf : tj);
        v = __float2half(src[n * 64]);
    } else {
        v = (q == 1 ? d_P1 : d_P2)[n * 256 + c * 64];
    }
    d_S[n * 400 + 384 + a] = v;
}

// ---------------- split-K GEMM with fused final reduce -------------------------
// C = A[4096,K] @ B[K, Nc], BM=BN=128, BK=32, grid (Nc/128, 32, 4), 256 threads.
// Partials (fp32) -> d_Part; last-arriving CTA per (x,y) tile sums 4 slabs -> fp16 Out.
__global__ void __launch_bounds__(256) gemmSK(const __half* __restrict__ Ag, int lda,
                                              const __half* __restrict__ Bg, int ldb,
                                              float* __restrict__ Part, int ldc,
                                              __half* __restrict__ Out, int ldo, int out_off,
                                              int K) {
    __shared__ __half sA[2][128][40];
    __shared__ __half sB[2][32][136];
    const int tid = threadIdx.x;
    const int lane = tid & 31, w = tid >> 5;
    const int wm = w >> 1, wn = w & 1;
    const int g = lane >> 2, tig = lane & 3;
    const int lm = lane & 15, hi = lane >> 4;
    const int row0 = blockIdx.y * 128;
    const int col0 = blockIdx.x * 128;
    const int Kc = K >> 2;
    const int kbase = blockIdx.z * Kc;
    const int NIT = Kc / 32;
    float* Cg = Part + (size_t)blockIdx.z * NN * ldc;

    uint32_t sAb = (uint32_t)__cvta_generic_to_shared(&sA[0][0][0]);
    uint32_t sBb = (uint32_t)__cvta_generic_to_shared(&sB[0][0][0]);

    float acc[2][8][4];
#pragma unroll
    for (int a = 0; a < 2; a++)
#pragma unroll
        for (int b = 0; b < 8; b++)
#pragma unroll
            for (int c = 0; c < 4; c++) acc[a][b][c] = 0.f;

    auto load_stage = [&](int s, int it) {
        int kg = kbase + it * 32;
        uint32_t aS = sAb + s * 10240;
        uint32_t bS = sBb + s * 8704;
#pragma unroll
        for (int ch = tid; ch < 512; ch += 256) {
            int r = ch >> 2, c = (ch & 3) << 3;
            CPA16(aS + (uint32_t)(r * 40 + c) * 2, Ag + (size_t)(row0 + r) * lda + kg + c);
        }
#pragma unroll
        for (int ch = tid; ch < 512; ch += 256) {
            int r = ch >> 4, c = (ch & 15) << 3;
            CPA16(bS + (uint32_t)(r * 136 + c) * 2, Bg + (size_t)(kg + r) * ldb + col0 + c);
        }
    };

    load_stage(0, 0);
    CPCOMMIT();

    for (int it = 0; it < NIT; it++) {
        if (it + 1 < NIT) {
            load_stage((it + 1) & 1, it + 1);
            CPCOMMIT();
            asm volatile("cp.async.wait_group 1;\n" ::);
        } else {
            asm volatile("cp.async.wait_group 0;\n" ::);
        }
        __syncthreads();

        int s = it & 1;
        uint32_t aS = sAb + s * 10240;
        uint32_t bS = sBb + s * 8704;
#pragma unroll
        for (int ks = 0; ks < 2; ks++) {
            int kk = ks * 16;
            uint32_t Af[2][4];
#pragma unroll
            for (int ms = 0; ms < 2; ms++) {
                int rm = wm * 32 + ms * 16;
                uint32_t addr = aS + (uint32_t)((rm + lm) * 40 + kk + hi * 8) * 2;
                asm volatile("ldmatrix.sync.aligned.m8n8.x4.shared.b16 {%0,%1,%2,%3},[%4];\n"
                             : "=r"(Af[ms][0]), "=r"(Af[ms][1]), "=r"(Af[ms][2]), "=r"(Af[ms][3])
                             : "r"(addr));
            }
            uint32_t Bf[8][2];
#pragma unroll
            for (int nb = 0; nb < 4; nb++) {
                int cn = wn * 64 + nb * 16;
                uint32_t r0, r1, r2, r3;
                uint32_t addr = bS + (uint32_t)((kk + lm) * 136 + cn + hi * 8) * 2;
                asm volatile("ldmatrix.sync.aligned.m8n8.x4.trans.shared.b16 {%0,%1,%2,%3},[%4];\n"
                             : "=r"(r0), "=r"(r1), "=r"(r2), "=r"(r3) : "r"(addr));
                Bf[2*nb][0] = r0; Bf[2*nb][1] = r1;
                Bf[2*nb+1][0] = r2; Bf[2*nb+1][1] = r3;
            }
#pragma unroll
            for (int ms = 0; ms < 2; ms++)
#pragma unroll
                for (int ns = 0; ns < 8; ns++)
                    asm volatile(
                        "mma.sync.aligned.m16n8k16.row.col.f32.f16.f16.f32 "
                        "{%0,%1,%2,%3},{%4,%5,%6,%7},{%8,%9},{%0,%1,%2,%3};\n"
                        : "+f"(acc[ms][ns][0]), "+f"(acc[ms][ns][1]),
                          "+f"(acc[ms][ns][2]), "+f"(acc[ms][ns][3])
                        : "r"(Af[ms][0]), "r"(Af[ms][1]), "r"(Af[ms][2]), "r"(Af[ms][3]),
                          "r"(Bf[ns][0]), "r"(Bf[ns][1]));
        }
        __syncthreads();
    }

#pragma unroll
    for (int ms = 0; ms < 2; ms++) {
        int r = row0 + wm * 32 + ms * 16 + g;
#pragma unroll
        for (int ns = 0; ns < 8; ns++) {
            int c = col0 + wn * 64 + ns * 8 + tig * 2;
            *(float2*)&Cg[(size_t)r * ldc + c]       = make_float2(acc[ms][ns][0], acc[ms][ns][1]);
            *(float2*)&Cg[(size_t)(r + 8) * ldc + c] = make_float2(acc[ms][ns][2], acc[ms][ns][3]);
        }
    }

    // ---- fused split-K reduction: last CTA of this (x,y) tile sums the 4 slabs ----
    __shared__ unsigned s_old;
    __threadfence();
    __syncthreads();
    if (tid == 0) s_old = atomicAdd(&d_cnt[blockIdx.x * gridDim.y + blockIdx.y], 1u);
    __syncthreads();
    if ((s_old & 3u) == 3u) {
        __threadfence();
        const size_t slab = (size_t)NN * ldc;
        for (int e = tid; e < 128 * 64; e += 256) {
            int r = e >> 6, c = (e & 63) << 1;
            size_t off = (size_t)(row0 + r) * ldc + col0 + c;
            float2 s0 = *(const float2*)(Part + off);
            float2 s1 = *(const float2*)(Part + off + slab);
            float2 s2 = *(const float2*)(Part + off + 2 * slab);
            float2 s3 = *(const float2*)(Part + off + 3 * slab);
            float xx = s0.x + s1.x + s2.x + s3.x;
            float yy = s0.y + s1.y + s2.y + s3.y;
            *(__half2*)&Out[(size_t)(row0 + r) * ldo + out_off + col0 + c] = __floats2half2_rn(xx, yy);
        }
    }
}

// ---------------- fused M4 GEMM + softmax-mix + tanh -> msg --------------------
// C[4096,512] = S[4096,400] @ Wcat[400,512]; BM=32, BN=512, BK=16, 512 threads.
__global__ void __launch_bounds__(512) m4msg_kernel(const float* __restrict__ mix_b,
                                                    const float* __restrict__ path_bias) {
    __shared__ union {
        struct { __half A[2][32][24]; __half B[2][16][520]; } g;
        float stage[32][132];
    } sm;
    const int tid = threadIdx.x, lane = tid & 31, w = tid >> 5;
    const int wr = w >> 3, wc = w & 7, g = lane >> 2, tig = lane & 3;
    const int lm = lane & 15, hi = lane >> 4;
    const int row0 = blockIdx.x * 32;
    uint32_t sAb = (uint32_t)__cvta_generic_to_shared(&sm.g.A[0][0][0]);
    uint32_t sBb = (uint32_t)__cvta_generic_to_shared(&sm.g.B[0][0][0]);

    float acc[8][4];
#pragma unroll
    for (int a = 0; a < 8; a++)
#pragma unroll
        for (int b = 0; b < 4; b++) acc[a][b] = 0.f;

    auto load_stage = [&](int s, int it) {
        int k0 = it * 16;
        if (tid < 64) {
            int r = tid >> 1, c = (tid & 1) << 3;
            CPA16(sAb + (uint32_t)(s * 1536 + (r * 24 + c) * 2), d_S + (size_t)(row0 + r) * 400 + k0 + c);
        }
#pragma unroll
        for (int ch = tid; ch < 1024; ch += 512) {
            int r = ch >> 6, c = (ch & 63) << 3;
            CPA16(sBb + (uint32_t)(s * 16640 + (r * 520 + c) * 2), d_Wcat + (size_t)(k0 + r) * 512 + c);
        }
    };

    const int NIT = 25;
    load_stage(0, 0);
    CPCOMMIT();
    for (int it = 0; it < NIT; it++) {
        if (it + 1 < NIT) {
            load_stage((it + 1) & 1, it + 1);
            CPCOMMIT();
            asm volatile("cp.async.wait_group 1;\n" ::);
        } else {
            asm volatile("cp.async.wait_group 0;\n" ::);
        }
        __syncthreads();
        int s = it & 1;
        uint32_t Af[4];
        uint32_t aA = sAb + (uint32_t)(s * 1536 + ((wr * 16 + lm) * 24 + hi * 8) * 2);
        asm volatile("ldmatrix.sync.aligned.m8n8.x4.shared.b16 {%0,%1,%2,%3},[%4];\n"
                     : "=r"(Af[0]), "=r"(Af[1]), "=r"(Af[2]), "=r"(Af[3]) : "r"(aA));
        uint32_t Bf[8][2];
#pragma unroll
        for (int nb = 0; nb < 4; nb++) {
            uint32_t r0, r1, r2, r3;
            uint32_t bA = sBb + (uint32_t)(s * 16640 + (lm * 520 + wc * 64 + nb * 16 + hi * 8) * 2);
            asm volatile("ldmatrix.sync.aligned.m8n8.x4.trans.shared.b16 {%0,%1,%2,%3},[%4];\n"
                         : "=r"(r0), "=r"(r1), "=r"(r2), "=r"(r3) : "r"(bA));
            Bf[2*nb][0] = r0; Bf[2*nb][1] = r1;
            Bf[2*nb+1][0] = r2; Bf[2*nb+1][1] = r3;
        }
#pragma unroll
        for (int nt = 0; nt < 8; nt++)
            asm volatile(
                "mma.sync.aligned.m16n8k16.row.col.f32.f16.f16.f32 "
                "{%0,%1,%2,%3},{%4,%5,%6,%7},{%8,%9},{%0,%1,%2,%3};\n"
                : "+f"(acc[nt][0]), "+f"(acc[nt][1]), "+f"(acc[nt][2]), "+f"(acc[nt][3])
                : "r"(Af[0]), "r"(Af[1]), "r"(Af[2]), "r"(Af[3]),
                  "r"(Bf[nt][0]), "r"(Bf[nt][1]));
        __syncthreads();
    }

    // epilogue: softmax over paths + weighted tanh mix
    const int row = tid >> 4, sub = tid & 15, jp = sub << 3;
    const int n = row0 + row;
    float lg[4];
#pragma unroll
    for (int p = 0; p < 4; p++) lg[p] = d_logit[n * 4 + p] + mix_b[p] + path_bias[p];
    float mx = fmaxf(fmaxf(lg[0], lg[1]), fmaxf(lg[2], lg[3]));
    float e0 = expf(lg[0]-mx), e1 = expf(lg[1]-mx), e2 = expf(lg[2]-mx), e3 = expf(lg[3]-mx);
    float inv = 1.f / (e0 + e1 + e2 + e3);
    float wp[4] = {e0*inv, e1*inv, e2*inv, e3*inv};

    float msg[8] = {0,0,0,0,0,0,0,0};
#pragma unroll
    for (int p = 0; p < 4; p++) {
        if ((wc >> 1) == p) {
#pragma unroll
            for (int nt = 0; nt < 8; nt++) {
                int cl = (wc & 1) * 64 + nt * 8 + tig * 2;
                int r0 = wr * 16 + g;
                sm.stage[r0][cl]     = acc[nt][0];
                sm.stage[r0][cl + 1] = acc[nt][1];
                sm.stage[r0 + 8][cl]     = acc[nt][2];
                sm.stage[r0 + 8][cl + 1] = acc[nt][3];
            }
        }
        __syncthreads();
#pragma unroll
        for (int jj = 0; jj < 8; jj++)
            msg[jj] += wp[p] * tanhf(sm.stage[row][jp + jj]);
        __syncthreads();
    }
#pragma unroll
    for (int jj = 0; jj < 8; jj += 2)
        *(__half2*)&d_X[(size_t)n * 256 + jp + jj] = __floats2half2_rn(msg[jj], msg[jj + 1]);
}

// ---------------- fused gate GEMM + GRU + pred + next logits -------------------
// C[4096,512] = X[4096,256] @ W2[256,512]; BM=32, BN=512, BK=16, 512 threads.
__global__ void __launch_bounds__(512) gate_kernel(const float* __restrict__ x_seq,
                                                   const float* __restrict__ m_seq,
                                                   const float* __restrict__ tf_seq,
                                                   const float* __restrict__ tj_seq,
                                                   const float* __restrict__ W_ih,
                                                   const float* __restrict__ b_ih,
                                                   const float* __restrict__ b_hh,
                                                   const float* __restrict__ out_W,
                                                   const float* __restrict__ out_b,
                                                   const float* __restrict__ mix_W,
                                                   float* __restrict__ out, int t) {
    __shared__ union {
        struct { __half A[2][32][24]; __half B[2][16][520]; } g;
        float stage[32][132];
    } sm;
    const int tid = threadIdx.x, lane = tid & 31, w = tid >> 5;
    const int wr = w >> 3, wc = w & 7, g = lane >> 2, tig = lane & 3;
    const int lm = lane & 15, hi = lane >> 4;
    const int row0 = blockIdx.x * 32;
    uint32_t sAb = (uint32_t)__cvta_generic_to_shared(&sm.g.A[0][0][0]);
    uint32_t sBb = (uint32_t)__cvta_generic_to_shared(&sm.g.B[0][0][0]);

    float acc[8][4];
#pragma unroll
    for (int a = 0; a < 8; a++)
#pragma unroll
        for (int b = 0; b < 4; b++) acc[a][b] = 0.f;

    auto load_stage = [&](int s, int it) {
        int k0 = it * 16;
        if (tid < 64) {
            int r = tid >> 1, c = (tid & 1) << 3;
            CPA16(sAb + (uint32_t)(s * 1536 + (r * 24 + c) * 2), d_X + (size_t)(row0 + r) * 256 + k0 + c);
        }
#pragma unroll
        for (int ch = tid; ch < 1024; ch += 512) {
            int r = ch >> 6, c = (ch & 63) << 3;
            CPA16(sBb + (uint32_t)(s * 16640 + (r * 520 + c) * 2), d_W2 + (size_t)(k0 + r) * 512 + c);
        }
    };

    const int NIT = 16;
    load_stage(0, 0);
    CPCOMMIT();
    for (int it = 0; it < NIT; it++) {
        if (it + 1 < NIT) {
            load_stage((it + 1) & 1, it + 1);
            CPCOMMIT();
            asm volatile("cp.async.wait_group 1;\n" ::);
        } else {
            asm volatile("cp.async.wait_group 0;\n" ::);
        }
        __syncthreads();
        int s = it & 1;
        uint32_t Af[4];
        uint32_t aA = sAb + (uint32_t)(s * 1536 + ((wr * 16 + lm) * 24 + hi * 8) * 2);
        asm volatile("ldmatrix.sync.aligned.m8n8.x4.shared.b16 {%0,%1,%2,%3},[%4];\n"
                     : "=r"(Af[0]), "=r"(Af[1]), "=r"(Af[2]), "=r"(Af[3]) : "r"(aA));
        uint32_t Bf[8][2];
#pragma unroll
        for (int nb = 0; nb < 4; nb++) {
            uint32_t r0, r1, r2, r3;
            uint32_t bA = sBb + (uint32_t)(s * 16640 + (lm * 520 + wc * 64 + nb * 16 + hi * 8) * 2);
            asm volatile("ldmatrix.sync.aligned.m8n8.x4.trans.shared.b16 {%0,%1,%2,%3},[%4];\n"
                         : "=r"(r0), "=r"(r1), "=r"(r2), "=r"(r3) : "r"(bA));
            Bf[2*nb][0] = r0; Bf[2*nb][1] = r1;
            Bf[2*nb+1][0] = r2; Bf[2*nb+1][1] = r3;
        }
#pragma unroll
        for (int nt = 0; nt < 8; nt++)
            asm volatile(
                "mma.sync.aligned.m16n8k16.row.col.f32.f16.f16.f32 "
                "{%0,%1,%2,%3},{%4,%5,%6,%7},{%8,%9},{%0,%1,%2,%3};\n"
                : "+f"(acc[nt][0]), "+f"(acc[nt][1]), "+f"(acc[nt][2]), "+f"(acc[nt][3])
                : "r"(Af[0]), "r"(Af[1]), "r"(Af[2]), "r"(Af[3]),
                  "r"(Bf[nt][0]), "r"(Bf[nt][1]));
        __syncthreads();
    }

    // epilogue: gather 4 col-blocks per (row, j), GRU math, h/S/X update, reductions
    const int row = tid >> 4, sub = tid & 15, jp = sub << 3;
    const int n = row0 + row;
    float tmp[4][8];
#pragma unroll
    for (int q = 0; q < 4; q++) {
        if ((wc >> 1) == q) {
#pragma unroll
            for (int nt = 0; nt < 8; nt++) {
                int cl = (wc & 1) * 64 + nt * 8 + tig * 2;
                int r0 = wr * 16 + g;
                sm.stage[r0][cl]     = acc[nt][0];
                sm.stage[r0][cl + 1] = acc[nt][1];
                sm.stage[r0 + 8][cl]     = acc[nt][2];
                sm.stage[r0 + 8][cl + 1] = acc[nt][3];
            }
        }
        __syncthreads();
#pragma unroll
        for (int jj = 0; jj < 8; jj++) tmp[q][jj] = sm.stage[row][jp + jj];
        __syncthreads();
    }

    float xs = x_seq[n * 64 + t];
    float ms = m_seq[n * 64 + t];
    float tfs = tf_seq[n * 64 + t];
    float tjs = tj_seq[n * 64 + t];
    float mp = __half2float(d_P1[n * 256 + t]) * d_Dfac[n];
    float skip = (0.1f + 0.05f * (1.f - ms)) * (1.f - 0.3f * mp);

    float hnew[8];
#pragma unroll
    for (int jj = 0; jj < 8; jj++) {
        int j = jp + jj;
        float4 wr_ = *(const float4*)&W_ih[(size_t)j * GIN_ + 128];
        float4 wz_ = *(const float4*)&W_ih[(size_t)(128 + j) * GIN_ + 128];
        float4 wn_ = *(const float4*)&W_ih[(size_t)(256 + j) * GIN_ + 128];
        float rs = tmp[0][jj] + b_ih[j] + b_hh[j]
                 + xs*wr_.x + ms*wr_.y + tfs*wr_.z + tjs*wr_.w;
        float zs = tmp[1][jj] + b_ih[128 + j] + b_hh[128 + j]
                 + xs*wz_.x + ms*wz_.y + tfs*wz_.z + tjs*wz_.w;
        float in_ = tmp[2][jj] + b_ih[256 + j]
                 + xs*wn_.x + ms*wn_.y + tfs*wn_.z + tjs*wn_.w;
        float hn_ = tmp[3][jj] + b_hh[256 + j];
        float r = 1.f / (1.f + expf(-rs));
        float z = 1.f / (1.f + expf(-zs));
        float nc = tanhf(in_ + r * hn_);
        float hold = d_hst[n * 128 + j];
        float h2 = (1.f - z) * nc + z * hold + skip * hold;
        d_hst[n * 128 + j] = h2;
        __half hh = __float2half(h2);
        d_S[(size_t)n * 400 + j] = hh;
        d_X[(size_t)n * 256 + 128 + j] = hh;
        hnew[jj] = h2;
    }

    // 5 block reductions: pred + 4 logits (16 partials per row)
#pragma unroll
    for (int q = 0; q < 5; q++) {
        float v = 0.f;
        if (q == 0) {
#pragma unroll
            for (int jj = 0; jj < 8; jj++) v += hnew[jj] * out_W[jp + jj];
        } else {
#pragma unroll
            for (int jj = 0; jj < 8; jj++) v += hnew[jj] * mix_W[(q - 1) * 128 + jp + jj];
        }
        sm.stage[row][sub] = v;
        __syncthreads();
        if (sub == 0) {
            float s = 0.f;
#pragma unroll
            for (int k = 0; k < 16; k++) s += sm.stage[row][k];
            if (q == 0) out[n * 64 + t] = s + out_b[0];
            else        d_logit[n * 4 + (q - 1)] = s;
        }
        __syncthreads();
    }

    // aux columns of S for step t+1
    if (sub == 0 && t < 63) {
#pragma unroll
        for (int c = 0; c < 3; c++) {
            const float* src = (c == 0) ? m_seq : (c == 1 ? tf_seq : tj_seq);
            d_S[(size_t)n * 400 + 384 + c * 3]     = __float2half(src[n * 64 + t + 1]);
            d_S[(size_t)n * 400 + 384 + c * 3 + 1] = d_P1[n * 256 + c * 64 + t + 1];
            d_S[(size_t)n * 400 + 384 + c * 3 + 2] = d_P2[n * 256 + c * 64 + t + 1];
        }
    }
}

// ---------------- host launcher ----------------
extern "C" void kernel_launch(void* const* d_in, const int* in_sizes, int n_in,
                              void* d_out, int out_size) {
    const float* x_seq     = (const float*)d_in[0];
    const float* m_seq     = (const float*)d_in[1];
    const float* tf_seq    = (const float*)d_in[2];
    const float* tj_seq    = (const float*)d_in[3];
    const float* A         = (const float*)d_in[4];
    const float* W_msg     = (const float*)d_in[5];
    const float* b_msg     = (const float*)d_in[6];
    const float* path_bias = (const float*)d_in[7];
    const float* mix_W     = (const float*)d_in[8];
    const float* mix_b     = (const float*)d_in[9];
    const float* W_ih      = (const float*)d_in[10];
    const float* W_hh      = (const float*)d_in[11];
    const float* b_ih      = (const float*)d_in[12];
    const float* b_hh      = (const float*)d_in[13];
    const float* out_W     = (const float*)d_in[14];
    const float* out_b     = (const float*)d_in[15];
    float* out = (float*)d_out;

    void *pAh, *pU, *pP1, *pP2, *pS, *pPart;
    cudaGetSymbolAddress(&pAh, d_Ah);
    cudaGetSymbolAddress(&pU, d_U16);
    cudaGetSymbolAddress(&pP1, d_P1);
    cudaGetSymbolAddress(&pP2, d_P2);
    cudaGetSymbolAddress(&pS, d_S);
    cudaGetSymbolAddress(&pPart, d_Part);

    rownorm_kernel<<<NN, 256>>>(A);
    build_u_kernel<<<(NN * 256 + 255) / 256, 256>>>(m_seq, tf_seq, tj_seq);
    build_w_kernel<<<(400*512 + 256*512 + 255) / 256, 256>>>(W_msg, W_ih, W_hh, b_msg);
    init_kernel<<<(NN * 128 + 255) / 256, 256>>>();

    // P1 = Anorm @ U, P2 = Anorm @ P1 (Nc=256, split-K=4, fused reduce)
    gemmSK<<<dim3(2, 32, 4), 256>>>((const __half*)pAh, NN, (const __half*)pU, 256,
                                    (float*)pPart, 256, (__half*)pP1, 256, 0, NN);
    gemmSK<<<dim3(2, 32, 4), 256>>>((const __half*)pAh, NN, (const __half*)pP1, 256,
                                    (float*)pPart, 256, (__half*)pP2, 256, 0, NN);
    init_aux_kernel<<<(NN * 9 + 255) / 256, 256>>>(m_seq, tf_seq, tj_seq);

    for (int t = 0; t < TT; t++) {
        // G1 = Anorm @ h -> S cols 128..255
        gemmSK<<<dim3(1, 32, 4), 256>>>((const __half*)pAh, NN, (const __half*)pS, 400,
                                        (float*)pPart, 128, (__half*)pS, 400, 128, NN);
        // G2 = Anorm @ G1 -> S cols 256..383
        gemmSK<<<dim3(1, 32, 4), 256>>>((const __half*)pAh, NN, (const __half*)pS + 128, 400,
                                        (float*)pPart, 128, (__half*)pS, 400, 256, NN);
        // msg = softmax-mix(tanh(S @ Wcat)) -> X cols 0..127
        m4msg_kernel<<<128, 512>>>(mix_b, path_bias);
        // gates + GRU + pred + next logits + aux
        gate_kernel<<<128, 512>>>(x_seq, m_seq, tf_seq, tj_seq, W_ih, b_ih, b_hh,
                                  out_W, out_b, mix_W, out, t);
    }
}

// round 9
// speedup vs baseline: 1.1257x; 1.1257x over previous
#include <cuda_runtime.h>
#include <cuda_fp16.h>
#include <cstdint>

#define NN 4096
#define TT 64
#define DIN_ 131
#define GIN_ 132

// ---------------- static device workspace ----------------
__device__ __half d_Ah[(size_t)NN * NN];      // row-normalized A fp16 (33.5 MB)
__device__ float  d_Dfac[NN];                 // D/(D+1e-8)
__device__ __half d_U16[NN * 256];            // [n][c*64+t] c=m,tf,tj; cols 192.. zero
__device__ __half d_P1[NN * 256];             // Anorm @ U
__device__ __half d_P2[NN * 256];             // Anorm @ P1
__device__ __half d_S[NN * 384];              // [h | G1 | G2]
__device__ __half d_X[NN * 256];              // [msg | h]
__device__ float  d_hst[NN * 128];            // carried state fp32
__device__ float  d_M4[(size_t)NN * 640];     // S @ Wcat (mix logits at 512..515)
__device__ float  d_GG[(size_t)NN * 768];     // [gi_msg | gh]
__device__ float  d_Part[(size_t)4 * NN * 256]; // split-K partials
__device__ __half d_Wcat[384 * 640];          // folded Cheb weights + mix cols
__device__ float  d_WuC[3 * 3 * 4 * 128];     // folded Cheb weights (u part)
__device__ __half d_Wblk[256 * 768];          // block-diag [Wihm ; Whh]
__device__ unsigned d_barCnt;
__device__ unsigned d_barGen;

#define CPA16(dst, src) asm volatile("cp.async.cg.shared.global [%0], [%1], 16;\n" :: "r"(dst), "l"(src))
#define CPCOMMIT() asm volatile("cp.async.commit_group;\n" ::)

// ---------------- grid barrier (all 128 CTAs resident by construction) --------
__device__ __forceinline__ void gridbar() {
    __syncthreads();
    if (threadIdx.x == 0) {
        __threadfence();
        volatile unsigned* genp = &d_barGen;
        unsigned g = *genp;
        unsigned old = atomicAdd(&d_barCnt, 1);
        if (old == 127u) {
            d_barCnt = 0;
            __threadfence();
            atomicExch(&d_barGen, g + 1u);
        } else {
            while (*genp == g) { }
        }
        __threadfence();
    }
    __syncthreads();
}

// ---------------- prep kernels ----------------
__global__ void __launch_bounds__(256) rownorm_kernel(const float* __restrict__ A) {
    int n = blockIdx.x;
    const float* row = A + (size_t)n * NN;
    float s = 0.f;
    for (int j = threadIdx.x; j < NN; j += 256) s += row[j];
    __shared__ float red[256];
    red[threadIdx.x] = s;
    __syncthreads();
    for (int o = 128; o > 0; o >>= 1) {
        if (threadIdx.x < o) red[threadIdx.x] += red[threadIdx.x + o];
        __syncthreads();
    }
    float D = red[0];
    float Dinv = (D > 0.f) ? (1.0f / D) : 0.f;
    if (threadIdx.x == 0) d_Dfac[n] = D / (D + 1e-8f);
    __half* dst = d_Ah + (size_t)n * NN;
    for (int j = threadIdx.x; j < NN; j += 256) dst[j] = __float2half(row[j] * Dinv);
}

__global__ void __launch_bounds__(256) build_u_kernel(const float* __restrict__ m,
                                                      const float* __restrict__ tf,
                                                      const float* __restrict__ tj) {
    int i = blockIdx.x * 256 + threadIdx.x;
    if (i >= NN * 256) return;
    int n = i >> 8, c = i & 255;
    float v = 0.f;
    if (c < 64)        v = m[n * 64 + c];
    else if (c < 128)  v = tf[n * 64 + c - 64];
    else if (c < 192)  v = tj[n * 64 + c - 128];
    d_U16[i] = __float2half(v);
}

// W_msg layout [4][3][131][128]: ((p*3+k)*131 + d)*128 + j
__global__ void __launch_bounds__(256) build_w_kernel(const float* __restrict__ W_msg,
                                                      const float* __restrict__ W_ih,
                                                      const float* __restrict__ W_hh,
                                                      const float* __restrict__ mix_W) {
    int i = blockIdx.x * 256 + threadIdx.x;
    const int NWCAT = 384 * 640;
    const int NWUC  = 3 * 3 * 4 * 128;
    const int NWBLK = 256 * 768;
    if (i < NWCAT) {
        int d = i / 640, q = i - d * 640;
        float v = 0.f;
        if (q < 512) {
            int p = q >> 7, j = q & 127;
            int kc = d >> 7, c = d & 127;
            if (kc == 0)      v = W_msg[((p*3+0)*DIN_ + c)*128 + j] - W_msg[((p*3+2)*DIN_ + c)*128 + j];
            else if (kc == 1) v = W_msg[((p*3+1)*DIN_ + c)*128 + j];
            else              v = 2.f * W_msg[((p*3+2)*DIN_ + c)*128 + j];
        } else if (q < 516 && d < 128) {
            v = mix_W[(q - 512) * 128 + d];
        }
        d_Wcat[i] = __float2half(v);
    } else if (i < NWCAT + NWUC) {
        int r = i - NWCAT;
        int j = r & 127;
        int p = (r >> 7) & 3;
        int t2 = r >> 9;          // 0..8 = c*3 + which
        int which = t2 % 3;
        int c = t2 / 3;
        int dd = 128 + c;
        float v;
        if (which == 0)      v = W_msg[((p*3+0)*DIN_ + dd)*128 + j] - W_msg[((p*3+2)*DIN_ + dd)*128 + j];
        else if (which == 1) v = W_msg[((p*3+1)*DIN_ + dd)*128 + j];
        else                 v = 2.f * W_msg[((p*3+2)*DIN_ + dd)*128 + j];
        d_WuC[r] = v;
    } else if (i < NWCAT + NWUC + NWBLK) {
        int r = i - (NWCAT + NWUC);
        int d = r / 768, c = r - d * 768;
        float v = 0.f;
        if (d < 128) {
            if (c < 384) v = W_ih[(size_t)c * GIN_ + d];      // gi = msg @ W_ih[:, :128]^T
        } else {
            if (c >= 384) v = W_hh[(size_t)(c - 384) * 128 + (d - 128)];  // gh = h @ W_hh^T
        }
        d_Wblk[r] = __float2half(v);
    }
}

__global__ void __launch_bounds__(256) init_kernel() {
    int i = blockIdx.x * 256 + threadIdx.x;
    if (i >= NN * 128) return;
    int n = i >> 7, j = i & 127;
    d_hst[i] = 0.f;
    d_S[n * 384 + j] = __float2half(0.f);
    d_X[n * 256 + 128 + j] = __float2half(0.f);
}

// ---------------- fused double-diffusion kernel -------------------------------
// One launch computes Out1 = Anorm @ B1 and Out2 = Anorm @ Out1-region (chained),
// each as split-K(4) partials + grid-barrier + deterministic reduce.
// grid = (1, 32, 4) = 128 CTAs (each SM hosts at most one; all resident).
// NCB = number of 128-col blocks of the operand (1 for loop, 2 for P-prep).
template <int NCB>
__global__ void __launch_bounds__(256) diffuse(
        const __half* __restrict__ Bs1, int ldb1, __half* O1, int ldo1, int off1,
        const __half* __restrict__ Bs2, int ldb2, __half* O2, int ldo2, int off2) {
    extern __shared__ __half dsm[];
    const int tid = threadIdx.x;
    const int lane = tid & 31, w = tid >> 5;
    const int wm = w >> 1, wn = w & 1;
    const int g = lane >> 2, tig = lane & 3;
    const int lm = lane & 15, hi = lane >> 4;
    const int row0 = blockIdx.y * 128;
    const int bz = blockIdx.z;
    const int kbase = bz * 1024;
    const int W = NCB * 128;
    const size_t slab = (size_t)NN * W;
    uint32_t sAb = (uint32_t)__cvta_generic_to_shared(dsm);
    uint32_t sBb = sAb + 30720;

    for (int pass = 0; pass < 2; pass++) {
        const __half* Bsrc = pass ? Bs2 : Bs1;
        const int ldb = pass ? ldb2 : ldb1;
        __half* Out = pass ? O2 : O1;
        const int ldo = pass ? ldo2 : ldo1;
        const int off = pass ? off2 : off1;
        float* Pz = d_Part + (size_t)bz * slab;

        for (int cb = 0; cb < NCB; cb++) {
            const int col0 = cb * 128;
            float acc[2][8][4];
#pragma unroll
            for (int a = 0; a < 2; a++)
#pragma unroll
                for (int b = 0; b < 8; b++)
#pragma unroll
                    for (int c = 0; c < 4; c++) acc[a][b][c] = 0.f;

            auto load_stage = [&](int s, int it) {
                int kg = kbase + it * 32;
                uint32_t aS = sAb + s * 10240;
                uint32_t bS = sBb + s * 8704;
#pragma unroll
                for (int ch = tid; ch < 512; ch += 256) {
                    int r = ch >> 2, c = (ch & 3) << 3;
                    CPA16(aS + (uint32_t)(r * 40 + c) * 2, d_Ah + (size_t)(row0 + r) * NN + kg + c);
                }
#pragma unroll
                for (int ch = tid; ch < 512; ch += 256) {
                    int r = ch >> 4, c = (ch & 15) << 3;
                    CPA16(bS + (uint32_t)(r * 136 + c) * 2, Bsrc + (size_t)(kg + r) * ldb + col0 + c);
                }
            };

            load_stage(0, 0); CPCOMMIT();
            load_stage(1, 1); CPCOMMIT();

            for (int it = 0; it < 32; it++) {
                asm volatile("cp.async.wait_group 1;\n" ::);
                __syncthreads();
                if (it + 2 < 32) load_stage((it + 2) % 3, it + 2);
                CPCOMMIT();

                int s = it % 3;
                uint32_t aS = sAb + s * 10240;
                uint32_t bS = sBb + s * 8704;
#pragma unroll
                for (int ks = 0; ks < 2; ks++) {
                    int kk = ks * 16;
                    uint32_t Af[2][4];
#pragma unroll
                    for (int ms = 0; ms < 2; ms++) {
                        int rm = wm * 32 + ms * 16;
                        uint32_t addr = aS + (uint32_t)((rm + lm) * 40 + kk + hi * 8) * 2;
                        asm volatile("ldmatrix.sync.aligned.m8n8.x4.shared.b16 {%0,%1,%2,%3},[%4];\n"
                                     : "=r"(Af[ms][0]), "=r"(Af[ms][1]), "=r"(Af[ms][2]), "=r"(Af[ms][3])
                                     : "r"(addr));
                    }
                    uint32_t Bf[8][2];
#pragma unroll
                    for (int nb = 0; nb < 4; nb++) {
                        int cn = wn * 64 + nb * 16;
                        uint32_t r0, r1, r2, r3;
                        uint32_t addr = bS + (uint32_t)((kk + lm) * 136 + cn + hi * 8) * 2;
                        asm volatile("ldmatrix.sync.aligned.m8n8.x4.trans.shared.b16 {%0,%1,%2,%3},[%4];\n"
                                     : "=r"(r0), "=r"(r1), "=r"(r2), "=r"(r3) : "r"(addr));
                        Bf[2*nb][0] = r0; Bf[2*nb][1] = r1;
                        Bf[2*nb+1][0] = r2; Bf[2*nb+1][1] = r3;
                    }
#pragma unroll
                    for (int ms = 0; ms < 2; ms++)
#pragma unroll
                        for (int ns = 0; ns < 8; ns++)
                            asm volatile(
                                "mma.sync.aligned.m16n8k16.row.col.f32.f16.f16.f32 "
                                "{%0,%1,%2,%3},{%4,%5,%6,%7},{%8,%9},{%0,%1,%2,%3};\n"
                                : "+f"(acc[ms][ns][0]), "+f"(acc[ms][ns][1]),
                                  "+f"(acc[ms][ns][2]), "+f"(acc[ms][ns][3])
                                : "r"(Af[ms][0]), "r"(Af[ms][1]), "r"(Af[ms][2]), "r"(Af[ms][3]),
                                  "r"(Bf[ns][0]), "r"(Bf[ns][1]));
                }
                __syncthreads();
            }

#pragma unroll
            for (int ms = 0; ms < 2; ms++) {
                int r = row0 + wm * 32 + ms * 16 + g;
#pragma unroll
                for (int ns = 0; ns < 8; ns++) {
                    int c = col0 + wn * 64 + ns * 8 + tig * 2;
                    *(float2*)&Pz[(size_t)r * W + c]       = make_float2(acc[ms][ns][0], acc[ms][ns][1]);
                    *(float2*)&Pz[(size_t)(r + 8) * W + c] = make_float2(acc[ms][ns][2], acc[ms][ns][3]);
                }
            }
        }

        gridbar();   // all partials of this pass visible

        // deterministic reduce: 128 CTAs each own 4096*NCB contiguous elements
        {
            const unsigned cta = (unsigned)(bz * 32 + blockIdx.y);
#pragma unroll
            for (int k = 0; k < 4 * NCB; k++) {
                size_t e = (size_t)cta * (4096 * NCB) + (size_t)(k * 256 + tid) * 4;
                int n = (int)(e / W);
                int c = (int)(e - (size_t)n * W);
                const float* p = d_Part + (size_t)n * W + c;
                float4 s0, s1, s2, s3;
                asm volatile("ld.global.cg.v4.f32 {%0,%1,%2,%3},[%4];"
                             : "=f"(s0.x), "=f"(s0.y), "=f"(s0.z), "=f"(s0.w) : "l"(p));
                asm volatile("ld.global.cg.v4.f32 {%0,%1,%2,%3},[%4];"
                             : "=f"(s1.x), "=f"(s1.y), "=f"(s1.z), "=f"(s1.w) : "l"(p + slab));
                asm volatile("ld.global.cg.v4.f32 {%0,%1,%2,%3},[%4];"
                             : "=f"(s2.x), "=f"(s2.y), "=f"(s2.z), "=f"(s2.w) : "l"(p + 2 * slab));
                asm volatile("ld.global.cg.v4.f32 {%0,%1,%2,%3},[%4];"
                             : "=f"(s3.x), "=f"(s3.y), "=f"(s3.z), "=f"(s3.w) : "l"(p + 3 * slab));
                float x0 = s0.x + s1.x + s2.x + s3.x;
                float x1 = s0.y + s1.y + s2.y + s3.y;
                float x2 = s0.z + s1.z + s2.z + s3.z;
                float x3 = s0.w + s1.w + s2.w + s3.w;
                __half* o = Out + (size_t)n * ldo + off + c;
                *(__half2*)o       = __floats2half2_rn(x0, x1);
                *(__half2*)(o + 2) = __floats2half2_rn(x2, x3);
            }
        }

        gridbar();   // reduce output visible before next pass overwrites Part
    }
}

// ---------------- 2-stage TC GEMM (fp32 out): C = A @ B ------------------------
__global__ void __launch_bounds__(256) gemmF(const __half* __restrict__ Ag, int lda,
                                             const __half* __restrict__ Bg, int ldb,
                                             float* __restrict__ Cg, int ldc, int K) {
    __shared__ __half sA[2][128][40];
    __shared__ __half sB[2][32][136];
    const int tid = threadIdx.x;
    const int lane = tid & 31, w = tid >> 5;
    const int wm = w >> 1, wn = w & 1;
    const int g = lane >> 2, tig = lane & 3;
    const int lm = lane & 15, hi = lane >> 4;
    const int row0 = blockIdx.y * 128;
    const int col0 = blockIdx.x * 128;
    const int NIT = K / 32;

    uint32_t sAb = (uint32_t)__cvta_generic_to_shared(&sA[0][0][0]);
    uint32_t sBb = (uint32_t)__cvta_generic_to_shared(&sB[0][0][0]);

    float acc[2][8][4];
#pragma unroll
    for (int a = 0; a < 2; a++)
#pragma unroll
        for (int b = 0; b < 8; b++)
#pragma unroll
            for (int c = 0; c < 4; c++) acc[a][b][c] = 0.f;

    auto load_stage = [&](int s, int it) {
        int kg = it * 32;
        uint32_t aS = sAb + s * 10240;
        uint32_t bS = sBb + s * 8704;
#pragma unroll
        for (int ch = tid; ch < 512; ch += 256) {
            int r = ch >> 2, c = (ch & 3) << 3;
            CPA16(aS + (uint32_t)(r * 40 + c) * 2, Ag + (size_t)(row0 + r) * lda + kg + c);
        }
#pragma unroll
        for (int ch = tid; ch < 512; ch += 256) {
            int r = ch >> 4, c = (ch & 15) << 3;
            CPA16(bS + (uint32_t)(r * 136 + c) * 2, Bg + (size_t)(kg + r) * ldb + col0 + c);
        }
    };

    load_stage(0, 0);
    CPCOMMIT();

    for (int it = 0; it < NIT; it++) {
        if (it + 1 < NIT) {
            load_stage((it + 1) & 1, it + 1);
            CPCOMMIT();
            asm volatile("cp.async.wait_group 1;\n" ::);
        } else {
            asm volatile("cp.async.wait_group 0;\n" ::);
        }
        __syncthreads();

        int s = it & 1;
        uint32_t aS = sAb + s * 10240;
        uint32_t bS = sBb + s * 8704;
#pragma unroll
        for (int ks = 0; ks < 2; ks++) {
            int kk = ks * 16;
            uint32_t Af[2][4];
#pragma unroll
            for (int ms = 0; ms < 2; ms++) {
                int rm = wm * 32 + ms * 16;
                uint32_t addr = aS + (uint32_t)((rm + lm) * 40 + kk + hi * 8) * 2;
                asm volatile("ldmatrix.sync.aligned.m8n8.x4.shared.b16 {%0,%1,%2,%3},[%4];\n"
                             : "=r"(Af[ms][0]), "=r"(Af[ms][1]), "=r"(Af[ms][2]), "=r"(Af[ms][3])
                             : "r"(addr));
            }
            uint32_t Bf[8][2];
#pragma unroll
            for (int nb = 0; nb < 4; nb++) {
                int cn = wn * 64 + nb * 16;
                uint32_t r0, r1, r2, r3;
                uint32_t addr = bS + (uint32_t)((kk + lm) * 136 + cn + hi * 8) * 2;
                asm volatile("ldmatrix.sync.aligned.m8n8.x4.trans.shared.b16 {%0,%1,%2,%3},[%4];\n"
                             : "=r"(r0), "=r"(r1), "=r"(r2), "=r"(r3) : "r"(addr));
                Bf[2*nb][0] = r0; Bf[2*nb][1] = r1;
                Bf[2*nb+1][0] = r2; Bf[2*nb+1][1] = r3;
            }
#pragma unroll
            for (int ms = 0; ms < 2; ms++)
#pragma unroll
                for (int ns = 0; ns < 8; ns++)
                    asm volatile(
                        "mma.sync.aligned.m16n8k16.row.col.f32.f16.f16.f32 "
                        "{%0,%1,%2,%3},{%4,%5,%6,%7},{%8,%9},{%0,%1,%2,%3};\n"
                        : "+f"(acc[ms][ns][0]), "+f"(acc[ms][ns][1]),
                          "+f"(acc[ms][ns][2]), "+f"(acc[ms][ns][3])
                        : "r"(Af[ms][0]), "r"(Af[ms][1]), "r"(Af[ms][2]), "r"(Af[ms][3]),
                          "r"(Bf[ns][0]), "r"(Bf[ns][1]));
        }
        __syncthreads();
    }

#pragma unroll
    for (int ms = 0; ms < 2; ms++) {
        int r = row0 + wm * 32 + ms * 16 + g;
#pragma unroll
        for (int ns = 0; ns < 8; ns++) {
            int c = col0 + wn * 64 + ns * 8 + tig * 2;
            *(float2*)&Cg[(size_t)r * ldc + c]       = make_float2(acc[ms][ns][0], acc[ms][ns][1]);
            *(float2*)&Cg[(size_t)(r + 8) * ldc + c] = make_float2(acc[ms][ns][2], acc[ms][ns][3]);
        }
    }
}

// ---------------- per-step elementwise A: m4 + softmax mix -> msg ---------------
__global__ void __launch_bounds__(256) step_msg(const float* __restrict__ m_seq,
                                                const float* __restrict__ tf_seq,
                                                const float* __restrict__ tj_seq,
                                                const float* __restrict__ b_msg,
                                                const float* __restrict__ mix_b,
                                                const float* __restrict__ path_bias,
                                                int t) {
    int i = blockIdx.x * 256 + threadIdx.x;
    if (i >= NN * 128) return;
    int n = i >> 7, j = i & 127;
    const float* m4n = d_M4 + (size_t)n * 640;

    float lg[4];
#pragma unroll
    for (int p = 0; p < 4; p++) lg[p] = m4n[512 + p] + mix_b[p] + path_bias[p];
    float mx = fmaxf(fmaxf(lg[0], lg[1]), fmaxf(lg[2], lg[3]));
    float e0 = expf(lg[0] - mx), e1 = expf(lg[1] - mx), e2 = expf(lg[2] - mx), e3 = expf(lg[3] - mx);
    float inv = 1.f / (e0 + e1 + e2 + e3);
    float wp[4] = {e0 * inv, e1 * inv, e2 * inv, e3 * inv};

    float u[3], p1c[3], p2c[3];
    u[0] = m_seq[n * TT + t];
    u[1] = tf_seq[n * TT + t];
    u[2] = tj_seq[n * TT + t];
#pragma unroll
    for (int c = 0; c < 3; c++) {
        p1c[c] = __half2float(d_P1[n * 256 + c * 64 + t]);
        p2c[c] = __half2float(d_P2[n * 256 + c * 64 + t]);
    }
    float msg = 0.f;
#pragma unroll
    for (int p = 0; p < 4; p++) {
        float a = m4n[p * 128 + j] + b_msg[p * 128 + j];
#pragma unroll
        for (int c = 0; c < 3; c++) {
            a += u[c]   * d_WuC[((c * 3 + 0) * 4 + p) * 128 + j];
            a += p1c[c] * d_WuC[((c * 3 + 1) * 4 + p) * 128 + j];
            a += p2c[c] * d_WuC[((c * 3 + 2) * 4 + p) * 128 + j];
        }
        msg += wp[p] * tanhf(a);
    }
    d_X[n * 256 + j] = __float2half(msg);
}

// ---------------- per-step elementwise B: GRU gates + skip + pred ---------------
__global__ void __launch_bounds__(128) step_gru(const float* __restrict__ x_seq,
                                                const float* __restrict__ m_seq,
                                                const float* __restrict__ tf_seq,
                                                const float* __restrict__ tj_seq,
                                                const float* __restrict__ W_ih,
                                                const float* __restrict__ b_ih,
                                                const float* __restrict__ b_hh,
                                                const float* __restrict__ out_W,
                                                const float* __restrict__ out_b,
                                                float* __restrict__ out, int t) {
    int n = blockIdx.x, j = threadIdx.x;
    float x = x_seq[n * TT + t];
    float m = m_seq[n * TT + t];
    float tf = tf_seq[n * TT + t];
    float tj = tj_seq[n * TT + t];
    float h = d_hst[n * 128 + j];

    const float* ggn = d_GG + (size_t)n * 768;
    float gi[3], gh[3];
#pragma unroll
    for (int q = 0; q < 3; q++) {
        int r = q * 128 + j;
        const float* wr = W_ih + (size_t)r * GIN_ + 128;
        gi[q] = ggn[r] + x * wr[0] + m * wr[1] + tf * wr[2] + tj * wr[3] + b_ih[r];
        gh[q] = ggn[384 + r] + b_hh[r];
    }
    float rg = 1.f / (1.f + expf(-(gi[0] + gh[0])));
    float z  = 1.f / (1.f + expf(-(gi[1] + gh[1])));
    float nc = tanhf(gi[2] + rg * gh[2]);
    float hn = (1.f - z) * nc + z * h;
    float mp = __half2float(d_P1[n * 256 + t]) * d_Dfac[n];
    float skip = (0.1f + 0.05f * (1.f - m)) * (1.f - 0.3f * mp);
    float h2 = hn + skip * h;

    d_hst[n * 128 + j] = h2;
    __half hh = __float2half(h2);
    d_S[n * 384 + j] = hh;
    d_X[n * 256 + 128 + j] = hh;

    __shared__ float sred[128];
    sred[j] = h2 * out_W[j];
    __syncthreads();
    for (int o = 64; o > 0; o >>= 1) {
        if (j < o) sred[j] += sred[j + o];
        __syncthreads();
    }
    if (j == 0) out[n * TT + t] = sred[0] + out_b[0];
}

// ---------------- host launcher ----------------
extern "C" void kernel_launch(void* const* d_in, const int* in_sizes, int n_in,
                              void* d_out, int out_size) {
    const float* x_seq     = (const float*)d_in[0];
    const float* m_seq     = (const float*)d_in[1];
    const float* tf_seq    = (const float*)d_in[2];
    const float* tj_seq    = (const float*)d_in[3];
    const float* A         = (const float*)d_in[4];
    const float* W_msg     = (const float*)d_in[5];
    const float* b_msg     = (const float*)d_in[6];
    const float* path_bias = (const float*)d_in[7];
    const float* mix_W     = (const float*)d_in[8];
    const float* mix_b     = (const float*)d_in[9];
    const float* W_ih      = (const float*)d_in[10];
    const float* W_hh      = (const float*)d_in[11];
    const float* b_ih      = (const float*)d_in[12];
    const float* b_hh      = (const float*)d_in[13];
    const float* out_W     = (const float*)d_in[14];
    const float* out_b     = (const float*)d_in[15];
    float* out = (float*)d_out;

    void *pU, *pP1, *pP2, *pS, *pX, *pM4, *pGG, *pWcat, *pWblk;
    cudaGetSymbolAddress(&pU, d_U16);
    cudaGetSymbolAddress(&pP1, d_P1);
    cudaGetSymbolAddress(&pP2, d_P2);
    cudaGetSymbolAddress(&pS, d_S);
    cudaGetSymbolAddress(&pX, d_X);
    cudaGetSymbolAddress(&pM4, d_M4);
    cudaGetSymbolAddress(&pGG, d_GG);
    cudaGetSymbolAddress(&pWcat, d_Wcat);
    cudaGetSymbolAddress(&pWblk, d_Wblk);

    const int DSM = 56832;
    cudaFuncSetAttribute(diffuse<1>, cudaFuncAttributeMaxDynamicSharedMemorySize, DSM);
    cudaFuncSetAttribute(diffuse<2>, cudaFuncAttributeMaxDynamicSharedMemorySize, DSM);

    build_u_kernel<<<(NN * 256 + 255) / 256, 256>>>(m_seq, tf_seq, tj_seq);
    build_w_kernel<<<(384*640 + 3*3*4*128 + 256*768 + 255) / 256, 256>>>(W_msg, W_ih, W_hh, mix_W);
    rownorm_kernel<<<NN, 256>>>(A);
    // P1 = Anorm @ U ; P2 = Anorm @ P1  (one fused launch; lands in profiler slot)
    diffuse<2><<<dim3(1, 32, 4), 256, DSM>>>((const __half*)pU, 256, (__half*)pP1, 256, 0,
                                             (const __half*)pP1, 256, (__half*)pP2, 256, 0);
    init_kernel<<<(NN * 128 + 255) / 256, 256>>>();

    for (int t = 0; t < TT; t++) {
        // G1 = Anorm @ h -> S[:,128:256] ; G2 = Anorm @ G1 -> S[:,256:384]
        diffuse<1><<<dim3(1, 32, 4), 256, DSM>>>((const __half*)pS, 384, (__half*)pS, 384, 128,
                                                 (const __half*)pS + 128, 384, (__half*)pS, 384, 256);
        // M4pre (+ mix logits) = S @ Wcat -> d_M4 [4096 x 640] fp32
        gemmF<<<dim3(5, 32), 256>>>((const __half*)pS, 384, (const __half*)pWcat, 640,
                                    (float*)pM4, 640, 384);
        step_msg<<<(NN * 128 + 255) / 256, 256>>>(m_seq, tf_seq, tj_seq, b_msg, mix_b, path_bias, t);
        // [gi_msg | gh] = X @ Wblk -> d_GG [4096 x 768] fp32
        gemmF<<<dim3(6, 32), 256>>>((const __half*)pX, 256, (const __half*)pWblk, 768,
                                    (float*)pGG, 768, 256);
        step_gru<<<NN, 128>>>(x_seq, m_seq, tf_seq, tj_seq, W_ih, b_ih, b_hh,
                              out_W, out_b, out, t);
    }
}

// round 10
// speedup vs baseline: 1.2270x; 1.0901x over previous
#include <cuda_runtime.h>
#include <cuda_fp16.h>
#include <cstdint>

#define NN 4096
#define TT 64
#define DIN_ 131
#define GIN_ 132
#define NSPLIT 8
#define NCTA 256

// ---------------- static device workspace ----------------
__device__ __half d_Ah[(size_t)NN * NN];      // row-normalized A fp16 (33.5 MB)
__device__ float  d_Dfac[NN];                 // D/(D+1e-8)
__device__ __half d_U16[NN * 256];            // [n][c*64+t] c=m,tf,tj; cols 192.. zero
__device__ __half d_P1[NN * 256];             // Anorm @ U
__device__ __half d_P2[NN * 256];             // Anorm @ P1
__device__ __half d_S[NN * 384];              // [h | G1 | G2]
__device__ __half d_X[NN * 256];              // [msg | h]
__device__ float  d_hst[NN * 128];            // carried state fp32
__device__ float  d_M4[(size_t)NN * 640];     // S @ Wcat (mix logits at 512..515)
__device__ float  d_GG[(size_t)NN * 768];     // [gi_msg | gh]
__device__ float  d_Part[(size_t)NSPLIT * NN * 256]; // split-K partials (33.5 MB)
__device__ __half d_Wcat[384 * 640];          // folded Cheb weights + mix cols
__device__ float  d_WuC[3 * 3 * 4 * 128];     // folded Cheb weights (u part)
__device__ __half d_Wblk[256 * 768];          // block-diag [Wihm ; Whh]
__device__ unsigned d_barCnt;
__device__ unsigned d_barGen;

#define CPA16(dst, src) asm volatile("cp.async.cg.shared.global [%0], [%1], 16;\n" :: "r"(dst), "l"(src))
#define CPCOMMIT() asm volatile("cp.async.commit_group;\n" ::)

// ---------------- grid barrier (all NCTA CTAs resident by construction) --------
__device__ __forceinline__ void gridbar() {
    __syncthreads();
    if (threadIdx.x == 0) {
        __threadfence();
        volatile unsigned* genp = &d_barGen;
        unsigned g = *genp;
        unsigned old = atomicAdd(&d_barCnt, 1);
        if (old == (NCTA - 1u)) {
            d_barCnt = 0;
            __threadfence();
            atomicExch(&d_barGen, g + 1u);
        } else {
            while (*genp == g) { }
        }
        __threadfence();
    }
    __syncthreads();
}

// ---------------- prep kernels ----------------
__global__ void __launch_bounds__(256) rownorm_kernel(const float* __restrict__ A) {
    int n = blockIdx.x;
    const float* row = A + (size_t)n * NN;
    float s = 0.f;
    for (int j = threadIdx.x; j < NN; j += 256) s += row[j];
    __shared__ float red[256];
    red[threadIdx.x] = s;
    __syncthreads();
    for (int o = 128; o > 0; o >>= 1) {
        if (threadIdx.x < o) red[threadIdx.x] += red[threadIdx.x + o];
        __syncthreads();
    }
    float D = red[0];
    float Dinv = (D > 0.f) ? (1.0f / D) : 0.f;
    if (threadIdx.x == 0) d_Dfac[n] = D / (D + 1e-8f);
    __half* dst = d_Ah + (size_t)n * NN;
    for (int j = threadIdx.x; j < NN; j += 256) dst[j] = __float2half(row[j] * Dinv);
}

__global__ void __launch_bounds__(256) build_u_kernel(const float* __restrict__ m,
                                                      const float* __restrict__ tf,
                                                      const float* __restrict__ tj) {
    int i = blockIdx.x * 256 + threadIdx.x;
    if (i >= NN * 256) return;
    int n = i >> 8, c = i & 255;
    float v = 0.f;
    if (c < 64)        v = m[n * 64 + c];
    else if (c < 128)  v = tf[n * 64 + c - 64];
    else if (c < 192)  v = tj[n * 64 + c - 128];
    d_U16[i] = __float2half(v);
}

// W_msg layout [4][3][131][128]: ((p*3+k)*131 + d)*128 + j
__global__ void __launch_bounds__(256) build_w_kernel(const float* __restrict__ W_msg,
                                                      const float* __restrict__ W_ih,
                                                      const float* __restrict__ W_hh,
                                                      const float* __restrict__ mix_W) {
    int i = blockIdx.x * 256 + threadIdx.x;
    const int NWCAT = 384 * 640;
    const int NWUC  = 3 * 3 * 4 * 128;
    const int NWBLK = 256 * 768;
    if (i < NWCAT) {
        int d = i / 640, q = i - d * 640;
        float v = 0.f;
        if (q < 512) {
            int p = q >> 7, j = q & 127;
            int kc = d >> 7, c = d & 127;
            if (kc == 0)      v = W_msg[((p*3+0)*DIN_ + c)*128 + j] - W_msg[((p*3+2)*DIN_ + c)*128 + j];
            else if (kc == 1) v = W_msg[((p*3+1)*DIN_ + c)*128 + j];
            else              v = 2.f * W_msg[((p*3+2)*DIN_ + c)*128 + j];
        } else if (q < 516 && d < 128) {
            v = mix_W[(q - 512) * 128 + d];
        }
        d_Wcat[i] = __float2half(v);
    } else if (i < NWCAT + NWUC) {
        int r = i - NWCAT;
        int j = r & 127;
        int p = (r >> 7) & 3;
        int t2 = r >> 9;          // 0..8 = c*3 + which
        int which = t2 % 3;
        int c = t2 / 3;
        int dd = 128 + c;
        float v;
        if (which == 0)      v = W_msg[((p*3+0)*DIN_ + dd)*128 + j] - W_msg[((p*3+2)*DIN_ + dd)*128 + j];
        else if (which == 1) v = W_msg[((p*3+1)*DIN_ + dd)*128 + j];
        else                 v = 2.f * W_msg[((p*3+2)*DIN_ + dd)*128 + j];
        d_WuC[r] = v;
    } else if (i < NWCAT + NWUC + NWBLK) {
        int r = i - (NWCAT + NWUC);
        int d = r / 768, c = r - d * 768;
        float v = 0.f;
        if (d < 128) {
            if (c < 384) v = W_ih[(size_t)c * GIN_ + d];      // gi = msg @ W_ih[:, :128]^T
        } else {
            if (c >= 384) v = W_hh[(size_t)(c - 384) * 128 + (d - 128)];  // gh = h @ W_hh^T
        }
        d_Wblk[r] = __float2half(v);
    }
}

__global__ void __launch_bounds__(256) init_kernel() {
    int i = blockIdx.x * 256 + threadIdx.x;
    if (i >= NN * 128) return;
    int n = i >> 7, j = i & 127;
    d_hst[i] = 0.f;
    d_S[n * 384 + j] = __float2half(0.f);
    d_X[n * 256 + 128 + j] = __float2half(0.f);
}

// ---------------- fused double-diffusion kernel -------------------------------
// One launch: Out1 = Anorm @ B1, then Out2 = Anorm @ (region produced by pass 1),
// each via split-K(8) partials + grid barrier + deterministic reduce.
// grid = (1, 32, 8) = 256 CTAs, 2 per SM (launch_bounds(256,2) caps regs at 128).
template <int NCB>
__global__ void __launch_bounds__(256, 2) diffuse(
        const __half* __restrict__ Bs1, int ldb1, __half* O1, int ldo1, int off1,
        const __half* __restrict__ Bs2, int ldb2, __half* O2, int ldo2, int off2) {
    extern __shared__ __half dsm[];
    const int tid = threadIdx.x;
    const int lane = tid & 31, w = tid >> 5;
    const int wm = w >> 1, wn = w & 1;
    const int g = lane >> 2, tig = lane & 3;
    const int lm = lane & 15, hi = lane >> 4;
    const int row0 = blockIdx.y * 128;
    const int bz = blockIdx.z;
    const int kbase = bz * (NN / NSPLIT);
    const int W = NCB * 128;
    const size_t slab = (size_t)NN * W;
    const int NIT = (NN / NSPLIT) / 32;     // 16
    uint32_t sAb = (uint32_t)__cvta_generic_to_shared(dsm);
    uint32_t sBb = sAb + 30720;

    for (int pass = 0; pass < 2; pass++) {
        const __half* Bsrc = pass ? Bs2 : Bs1;
        const int ldb = pass ? ldb2 : ldb1;
        __half* Out = pass ? O2 : O1;
        const int ldo = pass ? ldo2 : ldo1;
        const int off = pass ? off2 : off1;
        float* Pz = d_Part + (size_t)bz * slab;

        for (int cb = 0; cb < NCB; cb++) {
            const int col0 = cb * 128;
            float acc[2][8][4];
#pragma unroll
            for (int a = 0; a < 2; a++)
#pragma unroll
                for (int b = 0; b < 8; b++)
#pragma unroll
                    for (int c = 0; c < 4; c++) acc[a][b][c] = 0.f;

            auto load_stage = [&](int s, int it) {
                int kg = kbase + it * 32;
                uint32_t aS = sAb + s * 10240;
                uint32_t bS = sBb + s * 8704;
#pragma unroll
                for (int ch = tid; ch < 512; ch += 256) {
                    int r = ch >> 2, c = (ch & 3) << 3;
                    CPA16(aS + (uint32_t)(r * 40 + c) * 2, d_Ah + (size_t)(row0 + r) * NN + kg + c);
                }
#pragma unroll
                for (int ch = tid; ch < 512; ch += 256) {
                    int r = ch >> 4, c = (ch & 15) << 3;
                    CPA16(bS + (uint32_t)(r * 136 + c) * 2, Bsrc + (size_t)(kg + r) * ldb + col0 + c);
                }
            };

            load_stage(0, 0); CPCOMMIT();
            load_stage(1, 1); CPCOMMIT();

            for (int it = 0; it < NIT; it++) {
                asm volatile("cp.async.wait_group 1;\n" ::);
                __syncthreads();
                if (it + 2 < NIT) load_stage((it + 2) % 3, it + 2);
                CPCOMMIT();

                int s = it % 3;
                uint32_t aS = sAb + s * 10240;
                uint32_t bS = sBb + s * 8704;
#pragma unroll
                for (int ks = 0; ks < 2; ks++) {
                    int kk = ks * 16;
                    uint32_t Af[2][4];
#pragma unroll
                    for (int ms = 0; ms < 2; ms++) {
                        int rm = wm * 32 + ms * 16;
                        uint32_t addr = aS + (uint32_t)((rm + lm) * 40 + kk + hi * 8) * 2;
                        asm volatile("ldmatrix.sync.aligned.m8n8.x4.shared.b16 {%0,%1,%2,%3},[%4];\n"
                                     : "=r"(Af[ms][0]), "=r"(Af[ms][1]), "=r"(Af[ms][2]), "=r"(Af[ms][3])
                                     : "r"(addr));
                    }
                    uint32_t Bf[8][2];
#pragma unroll
                    for (int nb = 0; nb < 4; nb++) {
                        int cn = wn * 64 + nb * 16;
                        uint32_t r0, r1, r2, r3;
                        uint32_t addr = bS + (uint32_t)((kk + lm) * 136 + cn + hi * 8) * 2;
                        asm volatile("ldmatrix.sync.aligned.m8n8.x4.trans.shared.b16 {%0,%1,%2,%3},[%4];\n"
                                     : "=r"(r0), "=r"(r1), "=r"(r2), "=r"(r3) : "r"(addr));
                        Bf[2*nb][0] = r0; Bf[2*nb][1] = r1;
                        Bf[2*nb+1][0] = r2; Bf[2*nb+1][1] = r3;
                    }
#pragma unroll
                    for (int ms = 0; ms < 2; ms++)
#pragma unroll
                        for (int ns = 0; ns < 8; ns++)
                            asm volatile(
                                "mma.sync.aligned.m16n8k16.row.col.f32.f16.f16.f32 "
                                "{%0,%1,%2,%3},{%4,%5,%6,%7},{%8,%9},{%0,%1,%2,%3};\n"
                                : "+f"(acc[ms][ns][0]), "+f"(acc[ms][ns][1]),
                                  "+f"(acc[ms][ns][2]), "+f"(acc[ms][ns][3])
                                : "r"(Af[ms][0]), "r"(Af[ms][1]), "r"(Af[ms][2]), "r"(Af[ms][3]),
                                  "r"(Bf[ns][0]), "r"(Bf[ns][1]));
                }
                __syncthreads();
            }

#pragma unroll
            for (int ms = 0; ms < 2; ms++) {
                int r = row0 + wm * 32 + ms * 16 + g;
#pragma unroll
                for (int ns = 0; ns < 8; ns++) {
                    int c = col0 + wn * 64 + ns * 8 + tig * 2;
                    *(float2*)&Pz[(size_t)r * W + c]       = make_float2(acc[ms][ns][0], acc[ms][ns][1]);
                    *(float2*)&Pz[(size_t)(r + 8) * W + c] = make_float2(acc[ms][ns][2], acc[ms][ns][3]);
                }
            }
        }

        gridbar();   // all partials of this pass visible

        // deterministic reduce: 256 CTAs each own (NN*W)/256 contiguous elements
        {
            const unsigned cta = (unsigned)(bz * 32 + blockIdx.y);
#pragma unroll
            for (int k = 0; k < 2 * NCB; k++) {
                size_t e = (size_t)cta * (2048 * NCB) + (size_t)(k * 256 + tid) * 4;
                int n = (int)(e / W);
                int c = (int)(e - (size_t)n * W);
                const float* p = d_Part + (size_t)n * W + c;
                float x0 = 0.f, x1 = 0.f, x2 = 0.f, x3 = 0.f;
#pragma unroll
                for (int z = 0; z < NSPLIT; z++) {
                    float4 s4;
                    asm volatile("ld.global.cg.v4.f32 {%0,%1,%2,%3},[%4];"
                                 : "=f"(s4.x), "=f"(s4.y), "=f"(s4.z), "=f"(s4.w)
                                 : "l"(p + (size_t)z * slab));
                    x0 += s4.x; x1 += s4.y; x2 += s4.z; x3 += s4.w;
                }
                __half* o = Out + (size_t)n * ldo + off + c;
                *(__half2*)o       = __floats2half2_rn(x0, x1);
                *(__half2*)(o + 2) = __floats2half2_rn(x2, x3);
            }
        }

        if (pass == 0) gridbar();   // reduce output visible before pass 2 overwrites Part
    }
}

// ---------------- 2-stage TC GEMM (fp32 out): C = A @ B ------------------------
__global__ void __launch_bounds__(256) gemmF(const __half* __restrict__ Ag, int lda,
                                             const __half* __restrict__ Bg, int ldb,
                                             float* __restrict__ Cg, int ldc, int K) {
    __shared__ __half sA[2][128][40];
    __shared__ __half sB[2][32][136];
    const int tid = threadIdx.x;
    const int lane = tid & 31, w = tid >> 5;
    const int wm = w >> 1, wn = w & 1;
    const int g = lane >> 2, tig = lane & 3;
    const int lm = lane & 15, hi = lane >> 4;
    const int row0 = blockIdx.y * 128;
    const int col0 = blockIdx.x * 128;
    const int NIT = K / 32;

    uint32_t sAb = (uint32_t)__cvta_generic_to_shared(&sA[0][0][0]);
    uint32_t sBb = (uint32_t)__cvta_generic_to_shared(&sB[0][0][0]);

    float acc[2][8][4];
#pragma unroll
    for (int a = 0; a < 2; a++)
#pragma unroll
        for (int b = 0; b < 8; b++)
#pragma unroll
            for (int c = 0; c < 4; c++) acc[a][b][c] = 0.f;

    auto load_stage = [&](int s, int it) {
        int kg = it * 32;
        uint32_t aS = sAb + s * 10240;
        uint32_t bS = sBb + s * 8704;
#pragma unroll
        for (int ch = tid; ch < 512; ch += 256) {
            int r = ch >> 2, c = (ch & 3) << 3;
            CPA16(aS + (uint32_t)(r * 40 + c) * 2, Ag + (size_t)(row0 + r) * lda + kg + c);
        }
#pragma unroll
        for (int ch = tid; ch < 512; ch += 256) {
            int r = ch >> 4, c = (ch & 15) << 3;
            CPA16(bS + (uint32_t)(r * 136 + c) * 2, Bg + (size_t)(kg + r) * ldb + col0 + c);
        }
    };

    load_stage(0, 0);
    CPCOMMIT();

    for (int it = 0; it < NIT; it++) {
        if (it + 1 < NIT) {
            load_stage((it + 1) & 1, it + 1);
            CPCOMMIT();
            asm volatile("cp.async.wait_group 1;\n" ::);
        } else {
            asm volatile("cp.async.wait_group 0;\n" ::);
        }
        __syncthreads();

        int s = it & 1;
        uint32_t aS = sAb + s * 10240;
        uint32_t bS = sBb + s * 8704;
#pragma unroll
        for (int ks = 0; ks < 2; ks++) {
            int kk = ks * 16;
            uint32_t Af[2][4];
#pragma unroll
            for (int ms = 0; ms < 2; ms++) {
                int rm = wm * 32 + ms * 16;
                uint32_t addr = aS + (uint32_t)((rm + lm) * 40 + kk + hi * 8) * 2;
                asm volatile("ldmatrix.sync.aligned.m8n8.x4.shared.b16 {%0,%1,%2,%3},[%4];\n"
                             : "=r"(Af[ms][0]), "=r"(Af[ms][1]), "=r"(Af[ms][2]), "=r"(Af[ms][3])
                             : "r"(addr));
            }
            uint32_t Bf[8][2];
#pragma unroll
            for (int nb = 0; nb < 4; nb++) {
                int cn = wn * 64 + nb * 16;
                uint32_t r0, r1, r2, r3;
                uint32_t addr = bS + (uint32_t)((kk + lm) * 136 + cn + hi * 8) * 2;
                asm volatile("ldmatrix.sync.aligned.m8n8.x4.trans.shared.b16 {%0,%1,%2,%3},[%4];\n"
                             : "=r"(r0), "=r"(r1), "=r"(r2), "=r"(r3) : "r"(addr));
                Bf[2*nb][0] = r0; Bf[2*nb][1] = r1;
                Bf[2*nb+1][0] = r2; Bf[2*nb+1][1] = r3;
            }
#pragma unroll
            for (int ms = 0; ms < 2; ms++)
#pragma unroll
                for (int ns = 0; ns < 8; ns++)
                    asm volatile(
                        "mma.sync.aligned.m16n8k16.row.col.f32.f16.f16.f32 "
                        "{%0,%1,%2,%3},{%4,%5,%6,%7},{%8,%9},{%0,%1,%2,%3};\n"
                        : "+f"(acc[ms][ns][0]), "+f"(acc[ms][ns][1]),
                          "+f"(acc[ms][ns][2]), "+f"(acc[ms][ns][3])
                        : "r"(Af[ms][0]), "r"(Af[ms][1]), "r"(Af[ms][2]), "r"(Af[ms][3]),
                          "r"(Bf[ns][0]), "r"(Bf[ns][1]));
        }
        __syncthreads();
    }

#pragma unroll
    for (int ms = 0; ms < 2; ms++) {
        int r = row0 + wm * 32 + ms * 16 + g;
#pragma unroll
        for (int ns = 0; ns < 8; ns++) {
            int c = col0 + wn * 64 + ns * 8 + tig * 2;
            *(float2*)&Cg[(size_t)r * ldc + c]       = make_float2(acc[ms][ns][0], acc[ms][ns][1]);
            *(float2*)&Cg[(size_t)(r + 8) * ldc + c] = make_float2(acc[ms][ns][2], acc[ms][ns][3]);
        }
    }
}

// ---------------- per-step elementwise A: m4 + softmax mix -> msg ---------------
__global__ void __launch_bounds__(256) step_msg(const float* __restrict__ m_seq,
                                                const float* __restrict__ tf_seq,
                                                const float* __restrict__ tj_seq,
                                                const float* __restrict__ b_msg,
                                                const float* __restrict__ mix_b,
                                                const float* __restrict__ path_bias,
                                                int t) {
    int i = blockIdx.x * 256 + threadIdx.x;
    if (i >= NN * 128) return;
    int n = i >> 7, j = i & 127;
    const float* m4n = d_M4 + (size_t)n * 640;

    float lg[4];
#pragma unroll
    for (int p = 0; p < 4; p++) lg[p] = m4n[512 + p] + mix_b[p] + path_bias[p];
    float mx = fmaxf(fmaxf(lg[0], lg[1]), fmaxf(lg[2], lg[3]));
    float e0 = expf(lg[0] - mx), e1 = expf(lg[1] - mx), e2 = expf(lg[2] - mx), e3 = expf(lg[3] - mx);
    float inv = 1.f / (e0 + e1 + e2 + e3);
    float wp[4] = {e0 * inv, e1 * inv, e2 * inv, e3 * inv};

    float u[3], p1c[3], p2c[3];
    u[0] = m_seq[n * TT + t];
    u[1] = tf_seq[n * TT + t];
    u[2] = tj_seq[n * TT + t];
#pragma unroll
    for (int c = 0; c < 3; c++) {
        p1c[c] = __half2float(d_P1[n * 256 + c * 64 + t]);
        p2c[c] = __half2float(d_P2[n * 256 + c * 64 + t]);
    }
    float msg = 0.f;
#pragma unroll
    for (int p = 0; p < 4; p++) {
        float a = m4n[p * 128 + j] + b_msg[p * 128 + j];
#pragma unroll
        for (int c = 0; c < 3; c++) {
            a += u[c]   * d_WuC[((c * 3 + 0) * 4 + p) * 128 + j];
            a += p1c[c] * d_WuC[((c * 3 + 1) * 4 + p) * 128 + j];
            a += p2c[c] * d_WuC[((c * 3 + 2) * 4 + p) * 128 + j];
        }
        msg += wp[p] * tanhf(a);
    }
    d_X[n * 256 + j] = __float2half(msg);
}

// ---------------- per-step elementwise B: GRU gates + skip + pred ---------------
__global__ void __launch_bounds__(128) step_gru(const float* __restrict__ x_seq,
                                                const float* __restrict__ m_seq,
                                                const float* __restrict__ tf_seq,
                                                const float* __restrict__ tj_seq,
                                                const float* __restrict__ W_ih,
                                                const float* __restrict__ b_ih,
                                                const float* __restrict__ b_hh,
                                                const float* __restrict__ out_W,
                                                const float* __restrict__ out_b,
                                                float* __restrict__ out, int t) {
    int n = blockIdx.x, j = threadIdx.x;
    float x = x_seq[n * TT + t];
    float m = m_seq[n * TT + t];
    float tf = tf_seq[n * TT + t];
    float tj = tj_seq[n * TT + t];
    float h = d_hst[n * 128 + j];

    const float* ggn = d_GG + (size_t)n * 768;
    float gi[3], gh[3];
#pragma unroll
    for (int q = 0; q < 3; q++) {
        int r = q * 128 + j;
        const float* wr = W_ih + (size_t)r * GIN_ + 128;
        gi[q] = ggn[r] + x * wr[0] + m * wr[1] + tf * wr[2] + tj * wr[3] + b_ih[r];
        gh[q] = ggn[384 + r] + b_hh[r];
    }
    float rg = 1.f / (1.f + expf(-(gi[0] + gh[0])));
    float z  = 1.f / (1.f + expf(-(gi[1] + gh[1])));
    float nc = tanhf(gi[2] + rg * gh[2]);
    float hn = (1.f - z) * nc + z * h;
    float mp = __half2float(d_P1[n * 256 + t]) * d_Dfac[n];
    float skip = (0.1f + 0.05f * (1.f - m)) * (1.f - 0.3f * mp);
    float h2 = hn + skip * h;

    d_hst[n * 128 + j] = h2;
    __half hh = __float2half(h2);
    d_S[n * 384 + j] = hh;
    d_X[n * 256 + 128 + j] = hh;

    __shared__ float sred[128];
    sred[j] = h2 * out_W[j];
    __syncthreads();
    for (int o = 64; o > 0; o >>= 1) {
        if (j < o) sred[j] += sred[j + o];
        __syncthreads();
    }
    if (j == 0) out[n * TT + t] = sred[0] + out_b[0];
}

// ---------------- host launcher ----------------
extern "C" void kernel_launch(void* const* d_in, const int* in_sizes, int n_in,
                              void* d_out, int out_size) {
    const float* x_seq     = (const float*)d_in[0];
    const float* m_seq     = (const float*)d_in[1];
    const float* tf_seq    = (const float*)d_in[2];
    const float* tj_seq    = (const float*)d_in[3];
    const float* A         = (const float*)d_in[4];
    const float* W_msg     = (const float*)d_in[5];
    const float* b_msg     = (const float*)d_in[6];
    const float* path_bias = (const float*)d_in[7];
    const float* mix_W     = (const float*)d_in[8];
    const float* mix_b     = (const float*)d_in[9];
    const float* W_ih      = (const float*)d_in[10];
    const float* W_hh      = (const float*)d_in[11];
    const float* b_ih      = (const float*)d_in[12];
    const float* b_hh      = (const float*)d_in[13];
    const float* out_W     = (const float*)d_in[14];
    const float* out_b     = (const float*)d_in[15];
    float* out = (float*)d_out;

    void *pU, *pP1, *pP2, *pS, *pX, *pM4, *pGG, *pWcat, *pWblk;
    cudaGetSymbolAddress(&pU, d_U16);
    cudaGetSymbolAddress(&pP1, d_P1);
    cudaGetSymbolAddress(&pP2, d_P2);
    cudaGetSymbolAddress(&pS, d_S);
    cudaGetSymbolAddress(&pX, d_X);
    cudaGetSymbolAddress(&pM4, d_M4);
    cudaGetSymbolAddress(&pGG, d_GG);
    cudaGetSymbolAddress(&pWcat, d_Wcat);
    cudaGetSymbolAddress(&pWblk, d_Wblk);

    const int DSM = 56832;
    cudaFuncSetAttribute(diffuse<1>, cudaFuncAttributeMaxDynamicSharedMemorySize, DSM);
    cudaFuncSetAttribute(diffuse<2>, cudaFuncAttributeMaxDynamicSharedMemorySize, DSM);

    build_u_kernel<<<(NN * 256 + 255) / 256, 256>>>(m_seq, tf_seq, tj_seq);
    build_w_kernel<<<(384*640 + 3*3*4*128 + 256*768 + 255) / 256, 256>>>(W_msg, W_ih, W_hh, mix_W);
    rownorm_kernel<<<NN, 256>>>(A);
    // P1 = Anorm @ U ; P2 = Anorm @ P1  (one fused launch)
    diffuse<2><<<dim3(1, 32, NSPLIT), 256, DSM>>>((const __half*)pU, 256, (__half*)pP1, 256, 0,
                                                  (const __half*)pP1, 256, (__half*)pP2, 256, 0);
    init_kernel<<<(NN * 128 + 255) / 256, 256>>>();

    for (int t = 0; t < TT; t++) {
        // G1 = Anorm @ h -> S[:,128:256] ; G2 = Anorm @ G1 -> S[:,256:384]
        diffuse<1><<<dim3(1, 32, NSPLIT), 256, DSM>>>((const __half*)pS, 384, (__half*)pS, 384, 128,
                                                      (const __half*)pS + 128, 384, (__half*)pS, 384, 256);
        // M4pre (+ mix logits) = S @ Wcat -> d_M4 [4096 x 640] fp32
        gemmF<<<dim3(5, 32), 256>>>((const __half*)pS, 384, (const __half*)pWcat, 640,
                                    (float*)pM4, 640, 384);
        step_msg<<<(NN * 128 + 255) / 256, 256>>>(m_seq, tf_seq, tj_seq, b_msg, mix_b, path_bias, t);
        // [gi_msg | gh] = X @ Wblk -> d_GG [4096 x 768] fp32
        gemmF<<<dim3(6, 32), 256>>>((const __half*)pX, 256, (const __half*)pWblk, 768,
                                    (float*)pGG, 768, 256);
        step_gru<<<NN, 128>>>(x_seq, m_seq, tf_seq, tj_seq, W_ih, b_ih, b_hh,
                              out_W, out_b, out, t);
    }
}

// round 11
// speedup vs baseline: 1.2280x; 1.0008x over previous
#include <cuda_runtime.h>
#include <cuda_fp16.h>
#include <cstdint>

#define NN 4096
#define TT 64
#define DIN_ 131
#define GIN_ 132
#define NSPLIT 8
#define NCTA 256

// ---------------- static device workspace ----------------
__device__ __half d_Ah[(size_t)NN * NN];      // row-normalized A fp16 (33.5 MB)
__device__ float  d_Dfac[NN];                 // D/(D+1e-8)
__device__ __half d_U16[NN * 256];            // [n][c*64+t] c=m,tf,tj; cols 192.. zero
__device__ __half d_P1[NN * 256];             // Anorm @ U
__device__ __half d_P2[NN * 256];             // Anorm @ P1
__device__ __half d_S[NN * 384];              // [h | G1 | G2]
__device__ __half d_X[NN * 256];              // [msg | h]
__device__ float  d_hst[NN * 128];            // carried state fp32
__device__ float  d_M4[(size_t)NN * 640];     // S @ Wcat (mix logits at 512..515)
__device__ float  d_GG[(size_t)NN * 768];     // [gi_msg | gh]
__device__ float  d_Part[(size_t)NSPLIT * NN * 256]; // split-K partials (33.5 MB)
__device__ __half d_Wcat[384 * 640];          // folded Cheb weights + mix cols
__device__ float  d_WuC[3 * 3 * 4 * 128];     // folded Cheb weights (u part)
__device__ __half d_Wblk[256 * 768];          // block-diag [Wihm ; Whh]
__device__ unsigned d_barCnt;
__device__ unsigned d_barGen;

#define CPA16(dst, src) asm volatile("cp.async.cg.shared.global [%0], [%1], 16;\n" :: "r"(dst), "l"(src))
#define CPCOMMIT() asm volatile("cp.async.commit_group;\n" ::)

// A stage: 128 rows x 72 halves = 18432 B ; B stage: 64 rows x 136 halves = 17408 B
#define A_STAGE_B 18432
#define B_STAGE_B 17408
#define DSMEM_TOTAL (2 * (A_STAGE_B + B_STAGE_B))   // 71680

// ---------------- grid barrier (all NCTA CTAs resident by construction) --------
__device__ __forceinline__ void gridbar() {
    __syncthreads();
    if (threadIdx.x == 0) {
        __threadfence();
        volatile unsigned* genp = &d_barGen;
        unsigned g = *genp;
        unsigned old = atomicAdd(&d_barCnt, 1);
        if (old == (NCTA - 1u)) {
            d_barCnt = 0;
            __threadfence();
            atomicExch(&d_barGen, g + 1u);
        } else {
            while (*genp == g) { }
        }
        __threadfence();
    }
    __syncthreads();
}

// ---------------- prep kernels ----------------
__global__ void __launch_bounds__(256) rownorm_kernel(const float* __restrict__ A) {
    int n = blockIdx.x;
    const float* row = A + (size_t)n * NN;
    float s = 0.f;
    for (int j = threadIdx.x; j < NN; j += 256) s += row[j];
    __shared__ float red[256];
    red[threadIdx.x] = s;
    __syncthreads();
    for (int o = 128; o > 0; o >>= 1) {
        if (threadIdx.x < o) red[threadIdx.x] += red[threadIdx.x + o];
        __syncthreads();
    }
    float D = red[0];
    float Dinv = (D > 0.f) ? (1.0f / D) : 0.f;
    if (threadIdx.x == 0) d_Dfac[n] = D / (D + 1e-8f);
    __half* dst = d_Ah + (size_t)n * NN;
    for (int j = threadIdx.x; j < NN; j += 256) dst[j] = __float2half(row[j] * Dinv);
}

__global__ void __launch_bounds__(256) build_u_kernel(const float* __restrict__ m,
                                                      const float* __restrict__ tf,
                                                      const float* __restrict__ tj) {
    int i = blockIdx.x * 256 + threadIdx.x;
    if (i >= NN * 256) return;
    int n = i >> 8, c = i & 255;
    float v = 0.f;
    if (c < 64)        v = m[n * 64 + c];
    else if (c < 128)  v = tf[n * 64 + c - 64];
    else if (c < 192)  v = tj[n * 64 + c - 128];
    d_U16[i] = __float2half(v);
}

// W_msg layout [4][3][131][128]: ((p*3+k)*131 + d)*128 + j
__global__ void __launch_bounds__(256) build_w_kernel(const float* __restrict__ W_msg,
                                                      const float* __restrict__ W_ih,
                                                      const float* __restrict__ W_hh,
                                                      const float* __restrict__ mix_W) {
    int i = blockIdx.x * 256 + threadIdx.x;
    const int NWCAT = 384 * 640;
    const int NWUC  = 3 * 3 * 4 * 128;
    const int NWBLK = 256 * 768;
    if (i < NWCAT) {
        int d = i / 640, q = i - d * 640;
        float v = 0.f;
        if (q < 512) {
            int p = q >> 7, j = q & 127;
            int kc = d >> 7, c = d & 127;
            if (kc == 0)      v = W_msg[((p*3+0)*DIN_ + c)*128 + j] - W_msg[((p*3+2)*DIN_ + c)*128 + j];
            else if (kc == 1) v = W_msg[((p*3+1)*DIN_ + c)*128 + j];
            else              v = 2.f * W_msg[((p*3+2)*DIN_ + c)*128 + j];
        } else if (q < 516 && d < 128) {
            v = mix_W[(q - 512) * 128 + d];
        }
        d_Wcat[i] = __float2half(v);
    } else if (i < NWCAT + NWUC) {
        int r = i - NWCAT;
        int j = r & 127;
        int p = (r >> 7) & 3;
        int t2 = r >> 9;          // 0..8 = c*3 + which
        int which = t2 % 3;
        int c = t2 / 3;
        int dd = 128 + c;
        float v;
        if (which == 0)      v = W_msg[((p*3+0)*DIN_ + dd)*128 + j] - W_msg[((p*3+2)*DIN_ + dd)*128 + j];
        else if (which == 1) v = W_msg[((p*3+1)*DIN_ + dd)*128 + j];
        else                 v = 2.f * W_msg[((p*3+2)*DIN_ + dd)*128 + j];
        d_WuC[r] = v;
    } else if (i < NWCAT + NWUC + NWBLK) {
        int r = i - (NWCAT + NWUC);
        int d = r / 768, c = r - d * 768;
        float v = 0.f;
        if (d < 128) {
            if (c < 384) v = W_ih[(size_t)c * GIN_ + d];      // gi = msg @ W_ih[:, :128]^T
        } else {
            if (c >= 384) v = W_hh[(size_t)(c - 384) * 128 + (d - 128)];  // gh = h @ W_hh^T
        }
        d_Wblk[r] = __float2half(v);
    }
}

__global__ void __launch_bounds__(256) init_kernel() {
    int i = blockIdx.x * 256 + threadIdx.x;
    if (i >= NN * 128) return;
    int n = i >> 7, j = i & 127;
    d_hst[i] = 0.f;
    d_S[n * 384 + j] = __float2half(0.f);
    d_X[n * 256 + 128 + j] = __float2half(0.f);
}

// ---------------- fused double-diffusion kernel -------------------------------
// One launch: Out1 = Anorm @ B1, then Out2 = Anorm @ (region produced by pass 1),
// each via split-K(8) partials + grid barrier + deterministic reduce.
// grid = (1, 32, 8) = 256 CTAs, 2 per SM. BK=64, 2-stage, ONE sync per K-iter.
template <int NCB>
__global__ void __launch_bounds__(256, 2) diffuse(
        const __half* __restrict__ Bs1, int ldb1, __half* O1, int ldo1, int off1,
        const __half* __restrict__ Bs2, int ldb2, __half* O2, int ldo2, int off2) {
    extern __shared__ __half dsm[];
    const int tid = threadIdx.x;
    const int lane = tid & 31, w = tid >> 5;
    const int wm = w >> 1, wn = w & 1;
    const int g = lane >> 2, tig = lane & 3;
    const int lm = lane & 15, hi = lane >> 4;
    const int row0 = blockIdx.y * 128;
    const int bz = blockIdx.z;
    const int kbase = bz * (NN / NSPLIT);
    const int W = NCB * 128;
    const size_t slab = (size_t)NN * W;
    const int NIT = (NN / NSPLIT) / 64;     // 8
    uint32_t sAb = (uint32_t)__cvta_generic_to_shared(dsm);
    uint32_t sBb = sAb + 2 * A_STAGE_B;

    for (int pass = 0; pass < 2; pass++) {
        const __half* Bsrc = pass ? Bs2 : Bs1;
        const int ldb = pass ? ldb2 : ldb1;
        __half* Out = pass ? O2 : O1;
        const int ldo = pass ? ldo2 : ldo1;
        const int off = pass ? off2 : off1;
        float* Pz = d_Part + (size_t)bz * slab;

        for (int cb = 0; cb < NCB; cb++) {
            const int col0 = cb * 128;
            float acc[2][8][4];
#pragma unroll
            for (int a = 0; a < 2; a++)
#pragma unroll
                for (int b = 0; b < 8; b++)
#pragma unroll
                    for (int c = 0; c < 4; c++) acc[a][b][c] = 0.f;

            auto load_stage = [&](int s, int it) {
                int kg = kbase + it * 64;
                uint32_t aS = sAb + s * A_STAGE_B;
                uint32_t bS = sBb + s * B_STAGE_B;
                // A: 128 rows x 64 halves; 1024 16B-chunks, 4 per thread
#pragma unroll
                for (int ch = tid; ch < 1024; ch += 256) {
                    int r = ch >> 3, c = (ch & 7) << 3;
                    CPA16(aS + (uint32_t)(r * 72 + c) * 2, d_Ah + (size_t)(row0 + r) * NN + kg + c);
                }
                // B: 64 rows x 128 halves; 1024 chunks, 4 per thread
#pragma unroll
                for (int ch = tid; ch < 1024; ch += 256) {
                    int r = ch >> 4, c = (ch & 15) << 3;
                    CPA16(bS + (uint32_t)(r * 136 + c) * 2, Bsrc + (size_t)(kg + r) * ldb + col0 + c);
                }
            };

            load_stage(0, 0);
            CPCOMMIT();

            for (int it = 0; it < NIT; it++) {
                if (it + 1 < NIT) {
                    load_stage((it + 1) & 1, it + 1);
                    CPCOMMIT();
                    asm volatile("cp.async.wait_group 1;\n" ::);
                } else {
                    asm volatile("cp.async.wait_group 0;\n" ::);
                }
                __syncthreads();

                int s = it & 1;
                uint32_t aS = sAb + s * A_STAGE_B;
                uint32_t bS = sBb + s * B_STAGE_B;
#pragma unroll
                for (int ks = 0; ks < 4; ks++) {
                    int kk = ks * 16;
                    uint32_t Af[2][4];
#pragma unroll
                    for (int ms = 0; ms < 2; ms++) {
                        int rm = wm * 32 + ms * 16;
                        uint32_t addr = aS + (uint32_t)((rm + lm) * 72 + kk + hi * 8) * 2;
                        asm volatile("ldmatrix.sync.aligned.m8n8.x4.shared.b16 {%0,%1,%2,%3},[%4];\n"
                                     : "=r"(Af[ms][0]), "=r"(Af[ms][1]), "=r"(Af[ms][2]), "=r"(Af[ms][3])
                                     : "r"(addr));
                    }
                    uint32_t Bf[8][2];
#pragma unroll
                    for (int nb = 0; nb < 4; nb++) {
                        int cn = wn * 64 + nb * 16;
                        uint32_t r0, r1, r2, r3;
                        uint32_t addr = bS + (uint32_t)((kk + lm) * 136 + cn + hi * 8) * 2;
                        asm volatile("ldmatrix.sync.aligned.m8n8.x4.trans.shared.b16 {%0,%1,%2,%3},[%4];\n"
                                     : "=r"(r0), "=r"(r1), "=r"(r2), "=r"(r3) : "r"(addr));
                        Bf[2*nb][0] = r0; Bf[2*nb][1] = r1;
                        Bf[2*nb+1][0] = r2; Bf[2*nb+1][1] = r3;
                    }
#pragma unroll
                    for (int ms = 0; ms < 2; ms++)
#pragma unroll
                        for (int ns = 0; ns < 8; ns++)
                            asm volatile(
                                "mma.sync.aligned.m16n8k16.row.col.f32.f16.f16.f32 "
                                "{%0,%1,%2,%3},{%4,%5,%6,%7},{%8,%9},{%0,%1,%2,%3};\n"
                                : "+f"(acc[ms][ns][0]), "+f"(acc[ms][ns][1]),
                                  "+f"(acc[ms][ns][2]), "+f"(acc[ms][ns][3])
                                : "r"(Af[ms][0]), "r"(Af[ms][1]), "r"(Af[ms][2]), "r"(Af[ms][3]),
                                  "r"(Bf[ns][0]), "r"(Bf[ns][1]));
                }
                __syncthreads();
            }

#pragma unroll
            for (int ms = 0; ms < 2; ms++) {
                int r = row0 + wm * 32 + ms * 16 + g;
#pragma unroll
                for (int ns = 0; ns < 8; ns++) {
                    int c = col0 + wn * 64 + ns * 8 + tig * 2;
                    *(float2*)&Pz[(size_t)r * W + c]       = make_float2(acc[ms][ns][0], acc[ms][ns][1]);
                    *(float2*)&Pz[(size_t)(r + 8) * W + c] = make_float2(acc[ms][ns][2], acc[ms][ns][3]);
                }
            }
        }

        gridbar();   // all partials of this pass visible

        // deterministic reduce: 256 CTAs each own (NN*W)/256 contiguous elements
        {
            const unsigned cta = (unsigned)(bz * 32 + blockIdx.y);
#pragma unroll
            for (int k = 0; k < 2 * NCB; k++) {
                size_t e = (size_t)cta * (2048 * NCB) + (size_t)(k * 256 + tid) * 4;
                int n = (int)(e / W);
                int c = (int)(e - (size_t)n * W);
                const float* p = d_Part + (size_t)n * W + c;
                float x0 = 0.f, x1 = 0.f, x2 = 0.f, x3 = 0.f;
#pragma unroll
                for (int z = 0; z < NSPLIT; z++) {
                    float4 s4;
                    asm volatile("ld.global.cg.v4.f32 {%0,%1,%2,%3},[%4];"
                                 : "=f"(s4.x), "=f"(s4.y), "=f"(s4.z), "=f"(s4.w)
                                 : "l"(p + (size_t)z * slab));
                    x0 += s4.x; x1 += s4.y; x2 += s4.z; x3 += s4.w;
                }
                __half* o = Out + (size_t)n * ldo + off + c;
                *(__half2*)o       = __floats2half2_rn(x0, x1);
                *(__half2*)(o + 2) = __floats2half2_rn(x2, x3);
            }
        }

        if (pass == 0) gridbar();   // reduce output visible before pass 2 overwrites Part
    }
}

// ---------------- 2-stage TC GEMM (fp32 out): C = A @ B ------------------------
__global__ void __launch_bounds__(256) gemmF(const __half* __restrict__ Ag, int lda,
                                             const __half* __restrict__ Bg, int ldb,
                                             float* __restrict__ Cg, int ldc, int K) {
    __shared__ __half sA[2][128][40];
    __shared__ __half sB[2][32][136];
    const int tid = threadIdx.x;
    const int lane = tid & 31, w = tid >> 5;
    const int wm = w >> 1, wn = w & 1;
    const int g = lane >> 2, tig = lane & 3;
    const int lm = lane & 15, hi = lane >> 4;
    const int row0 = blockIdx.y * 128;
    const int col0 = blockIdx.x * 128;
    const int NIT = K / 32;

    uint32_t sAb = (uint32_t)__cvta_generic_to_shared(&sA[0][0][0]);
    uint32_t sBb = (uint32_t)__cvta_generic_to_shared(&sB[0][0][0]);

    float acc[2][8][4];
#pragma unroll
    for (int a = 0; a < 2; a++)
#pragma unroll
        for (int b = 0; b < 8; b++)
#pragma unroll
            for (int c = 0; c < 4; c++) acc[a][b][c] = 0.f;

    auto load_stage = [&](int s, int it) {
        int kg = it * 32;
        uint32_t aS = sAb + s * 10240;
        uint32_t bS = sBb + s * 8704;
#pragma unroll
        for (int ch = tid; ch < 512; ch += 256) {
            int r = ch >> 2, c = (ch & 3) << 3;
            CPA16(aS + (uint32_t)(r * 40 + c) * 2, Ag + (size_t)(row0 + r) * lda + kg + c);
        }
#pragma unroll
        for (int ch = tid; ch < 512; ch += 256) {
            int r = ch >> 4, c = (ch & 15) << 3;
            CPA16(bS + (uint32_t)(r * 136 + c) * 2, Bg + (size_t)(kg + r) * ldb + col0 + c);
        }
    };

    load_stage(0, 0);
    CPCOMMIT();

    for (int it = 0; it < NIT; it++) {
        if (it + 1 < NIT) {
            load_stage((it + 1) & 1, it + 1);
            CPCOMMIT();
            asm volatile("cp.async.wait_group 1;\n" ::);
        } else {
            asm volatile("cp.async.wait_group 0;\n" ::);
        }
        __syncthreads();

        int s = it & 1;
        uint32_t aS = sAb + s * 10240;
        uint32_t bS = sBb + s * 8704;
#pragma unroll
        for (int ks = 0; ks < 2; ks++) {
            int kk = ks * 16;
            uint32_t Af[2][4];
#pragma unroll
            for (int ms = 0; ms < 2; ms++) {
                int rm = wm * 32 + ms * 16;
                uint32_t addr = aS + (uint32_t)((rm + lm) * 40 + kk + hi * 8) * 2;
                asm volatile("ldmatrix.sync.aligned.m8n8.x4.shared.b16 {%0,%1,%2,%3},[%4];\n"
                             : "=r"(Af[ms][0]), "=r"(Af[ms][1]), "=r"(Af[ms][2]), "=r"(Af[ms][3])
                             : "r"(addr));
            }
            uint32_t Bf[8][2];
#pragma unroll
            for (int nb = 0; nb < 4; nb++) {
                int cn = wn * 64 + nb * 16;
                uint32_t r0, r1, r2, r3;
                uint32_t addr = bS + (uint32_t)((kk + lm) * 136 + cn + hi * 8) * 2;
                asm volatile("ldmatrix.sync.aligned.m8n8.x4.trans.shared.b16 {%0,%1,%2,%3},[%4];\n"
                             : "=r"(r0), "=r"(r1), "=r"(r2), "=r"(r3) : "r"(addr));
                Bf[2*nb][0] = r0; Bf[2*nb][1] = r1;
                Bf[2*nb+1][0] = r2; Bf[2*nb+1][1] = r3;
            }
#pragma unroll
            for (int ms = 0; ms < 2; ms++)
#pragma unroll
                for (int ns = 0; ns < 8; ns++)
                    asm volatile(
                        "mma.sync.aligned.m16n8k16.row.col.f32.f16.f16.f32 "
                        "{%0,%1,%2,%3},{%4,%5,%6,%7},{%8,%9},{%0,%1,%2,%3};\n"
                        : "+f"(acc[ms][ns][0]), "+f"(acc[ms][ns][1]),
                          "+f"(acc[ms][ns][2]), "+f"(acc[ms][ns][3])
                        : "r"(Af[ms][0]), "r"(Af[ms][1]), "r"(Af[ms][2]), "r"(Af[ms][3]),
                          "r"(Bf[ns][0]), "r"(Bf[ns][1]));
        }
        __syncthreads();
    }

#pragma unroll
    for (int ms = 0; ms < 2; ms++) {
        int r = row0 + wm * 32 + ms * 16 + g;
#pragma unroll
        for (int ns = 0; ns < 8; ns++) {
            int c = col0 + wn * 64 + ns * 8 + tig * 2;
            *(float2*)&Cg[(size_t)r * ldc + c]       = make_float2(acc[ms][ns][0], acc[ms][ns][1]);
            *(float2*)&Cg[(size_t)(r + 8) * ldc + c] = make_float2(acc[ms][ns][2], acc[ms][ns][3]);
        }
    }
}

// ---------------- per-step elementwise A: m4 + softmax mix -> msg ---------------
__global__ void __launch_bounds__(256) step_msg(const float* __restrict__ m_seq,
                                                const float* __restrict__ tf_seq,
                                                const float* __restrict__ tj_seq,
                                                const float* __restrict__ b_msg,
                                                const float* __restrict__ mix_b,
                                                const float* __restrict__ path_bias,
                                                int t) {
    int i = blockIdx.x * 256 + threadIdx.x;
    if (i >= NN * 128) return;
    int n = i >> 7, j = i & 127;
    const float* m4n = d_M4 + (size_t)n * 640;

    float lg[4];
#pragma unroll
    for (int p = 0; p < 4; p++) lg[p] = m4n[512 + p] + mix_b[p] + path_bias[p];
    float mx = fmaxf(fmaxf(lg[0], lg[1]), fmaxf(lg[2], lg[3]));
    float e0 = expf(lg[0] - mx), e1 = expf(lg[1] - mx), e2 = expf(lg[2] - mx), e3 = expf(lg[3] - mx);
    float inv = 1.f / (e0 + e1 + e2 + e3);
    float wp[4] = {e0 * inv, e1 * inv, e2 * inv, e3 * inv};

    float u[3], p1c[3], p2c[3];
    u[0] = m_seq[n * TT + t];
    u[1] = tf_seq[n * TT + t];
    u[2] = tj_seq[n * TT + t];
#pragma unroll
    for (int c = 0; c < 3; c++) {
        p1c[c] = __half2float(d_P1[n * 256 + c * 64 + t]);
        p2c[c] = __half2float(d_P2[n * 256 + c * 64 + t]);
    }
    float msg = 0.f;
#pragma unroll
    for (int p = 0; p < 4; p++) {
        float a = m4n[p * 128 + j] + b_msg[p * 128 + j];
#pragma unroll
        for (int c = 0; c < 3; c++) {
            a += u[c]   * d_WuC[((c * 3 + 0) * 4 + p) * 128 + j];
            a += p1c[c] * d_WuC[((c * 3 + 1) * 4 + p) * 128 + j];
            a += p2c[c] * d_WuC[((c * 3 + 2) * 4 + p) * 128 + j];
        }
        msg += wp[p] * tanhf(a);
    }
    d_X[n * 256 + j] = __float2half(msg);
}

// ---------------- per-step elementwise B: GRU gates + skip + pred ---------------
__global__ void __launch_bounds__(128) step_gru(const float* __restrict__ x_seq,
                                                const float* __restrict__ m_seq,
                                                const float* __restrict__ tf_seq,
                                                const float* __restrict__ tj_seq,
                                                const float* __restrict__ W_ih,
                                                const float* __restrict__ b_ih,
                                                const float* __restrict__ b_hh,
                                                const float* __restrict__ out_W,
                                                const float* __restrict__ out_b,
                                                float* __restrict__ out, int t) {
    int n = blockIdx.x, j = threadIdx.x;
    float x = x_seq[n * TT + t];
    float m = m_seq[n * TT + t];
    float tf = tf_seq[n * TT + t];
    float tj = tj_seq[n * TT + t];
    float h = d_hst[n * 128 + j];

    const float* ggn = d_GG + (size_t)n * 768;
    float gi[3], gh[3];
#pragma unroll
    for (int q = 0; q < 3; q++) {
        int r = q * 128 + j;
        const float* wr = W_ih + (size_t)r * GIN_ + 128;
        gi[q] = ggn[r] + x * wr[0] + m * wr[1] + tf * wr[2] + tj * wr[3] + b_ih[r];
        gh[q] = ggn[384 + r] + b_hh[r];
    }
    float rg = 1.f / (1.f + expf(-(gi[0] + gh[0])));
    float z  = 1.f / (1.f + expf(-(gi[1] + gh[1])));
    float nc = tanhf(gi[2] + rg * gh[2]);
    float hn = (1.f - z) * nc + z * h;
    float mp = __half2float(d_P1[n * 256 + t]) * d_Dfac[n];
    float skip = (0.1f + 0.05f * (1.f - m)) * (1.f - 0.3f * mp);
    float h2 = hn + skip * h;

    d_hst[n * 128 + j] = h2;
    __half hh = __float2half(h2);
    d_S[n * 384 + j] = hh;
    d_X[n * 256 + 128 + j] = hh;

    __shared__ float sred[128];
    sred[j] = h2 * out_W[j];
    __syncthreads();
    for (int o = 64; o > 0; o >>= 1) {
        if (j < o) sred[j] += sred[j + o];
        __syncthreads();
    }
    if (j == 0) out[n * TT + t] = sred[0] + out_b[0];
}

// ---------------- host launcher ----------------
extern "C" void kernel_launch(void* const* d_in, const int* in_sizes, int n_in,
                              void* d_out, int out_size) {
    const float* x_seq     = (const float*)d_in[0];
    const float* m_seq     = (const float*)d_in[1];
    const float* tf_seq    = (const float*)d_in[2];
    const float* tj_seq    = (const float*)d_in[3];
    const float* A         = (const float*)d_in[4];
    const float* W_msg     = (const float*)d_in[5];
    const float* b_msg     = (const float*)d_in[6];
    const float* path_bias = (const float*)d_in[7];
    const float* mix_W     = (const float*)d_in[8];
    const float* mix_b     = (const float*)d_in[9];
    const float* W_ih      = (const float*)d_in[10];
    const float* W_hh      = (const float*)d_in[11];
    const float* b_ih      = (const float*)d_in[12];
    const float* b_hh      = (const float*)d_in[13];
    const float* out_W     = (const float*)d_in[14];
    const float* out_b     = (const float*)d_in[15];
    float* out = (float*)d_out;

    void *pU, *pP1, *pP2, *pS, *pX, *pM4, *pGG, *pWcat, *pWblk;
    cudaGetSymbolAddress(&pU, d_U16);
    cudaGetSymbolAddress(&pP1, d_P1);
    cudaGetSymbolAddress(&pP2, d_P2);
    cudaGetSymbolAddress(&pS, d_S);
    cudaGetSymbolAddress(&pX, d_X);
    cudaGetSymbolAddress(&pM4, d_M4);
    cudaGetSymbolAddress(&pGG, d_GG);
    cudaGetSymbolAddress(&pWcat, d_Wcat);
    cudaGetSymbolAddress(&pWblk, d_Wblk);

    cudaFuncSetAttribute(diffuse<1>, cudaFuncAttributeMaxDynamicSharedMemorySize, DSMEM_TOTAL);
    cudaFuncSetAttribute(diffuse<2>, cudaFuncAttributeMaxDynamicSharedMemorySize, DSMEM_TOTAL);

    build_u_kernel<<<(NN * 256 + 255) / 256, 256>>>(m_seq, tf_seq, tj_seq);
    build_w_kernel<<<(384*640 + 3*3*4*128 + 256*768 + 255) / 256, 256>>>(W_msg, W_ih, W_hh, mix_W);
    rownorm_kernel<<<NN, 256>>>(A);
    // P1 = Anorm @ U ; P2 = Anorm @ P1  (one fused launch)
    diffuse<2><<<dim3(1, 32, NSPLIT), 256, DSMEM_TOTAL>>>((const __half*)pU, 256, (__half*)pP1, 256, 0,
                                                          (const __half*)pP1, 256, (__half*)pP2, 256, 0);
    init_kernel<<<(NN * 128 + 255) / 256, 256>>>();

    for (int t = 0; t < TT; t++) {
        // G1 = Anorm @ h -> S[:,128:256] ; G2 = Anorm @ G1 -> S[:,256:384]
        diffuse<1><<<dim3(1, 32, NSPLIT), 256, DSMEM_TOTAL>>>((const __half*)pS, 384, (__half*)pS, 384, 128,
                                                              (const __half*)pS + 128, 384, (__half*)pS, 384, 256);
        // M4pre (+ mix logits) = S @ Wcat -> d_M4 [4096 x 640] fp32
        gemmF<<<dim3(5, 32), 256>>>((const __half*)pS, 384, (const __half*)pWcat, 640,
                                    (float*)pM4, 640, 384);
        step_msg<<<(NN * 128 + 255) / 256, 256>>>(m_seq, tf_seq, tj_seq, b_msg, mix_b, path_bias, t);
        // [gi_msg | gh] = X @ Wblk -> d_GG [4096 x 768] fp32
        gemmF<<<dim3(6, 32), 256>>>((const __half*)pX, 256, (const __half*)pWblk, 768,
                                    (float*)pGG, 768, 256);
        step_gru<<<NN, 128>>>(x_seq, m_seq, tf_seq, tj_seq, W_ih, b_ih, b_hh,
                              out_W, out_b, out, t);
    }
}